// round 2
// baseline (speedup 1.0000x reference)
#include <cuda_runtime.h>
#include <cuda_bf16.h>
#include <math.h>

// Problem constants (fixed by setup_inputs)
#define B     4
#define N     2048
#define D     512
#define HEADS 8
#define DH    64
#define INNER 512   // HEADS*DH

// Band half-width: r <= 0.7645 -> r^64 ~ 3.4e-8, negligible vs 1e-3 tol
#define BW 64
#define RB 64      // query rows per band block

// -------- scratch (no allocations allowed) --------
__device__ float g_v[B * N * INNER];      // v = x @ W_v, layout (b, n, h*dh)
__device__ float g_attn[B * N * INNER];   // banded-softmax output, same layout
__device__ float g_inv[B * HEADS * N];    // 1/denom per (b,h,i)

// ============================================================
// SGEMM: C[M,Nc] = A[M,K] @ Bm[K,Nc] (+ bias[Nc] if bias != null)
// BM=128 BN=128 BK=16, 256 threads, 8x8 per-thread tile.
// Requires M%128==0, Nc%128==0, K%16==0 (true here).
// ============================================================
#define BM 128
#define BN 128
#define BKK 16
#define TM 8
#define TN 8

__global__ __launch_bounds__(256, 2)
void sgemm_kernel(const float* __restrict__ A, const float* __restrict__ Bm,
                  const float* __restrict__ bias, float* __restrict__ C,
                  int M, int Nc, int K)
{
    __shared__ float As[BKK][BM];   // transposed A tile: As[k][row]
    __shared__ float Bs[BKK][BN];

    const int tid = threadIdx.x;
    const int rowBase = blockIdx.y * BM;
    const int colBase = blockIdx.x * BN;

    // A-load mapping: 128 rows x 16 k, float4 along k
    const int aRow  = tid >> 2;          // 0..63
    const int aCol4 = (tid & 3) * 4;     // 0,4,8,12
    // B-load mapping: 16 k-rows x 128 cols, float4 along cols
    const int bRow  = tid >> 5;          // 0..7
    const int bCol4 = (tid & 31) * 4;    // 0..124

    const int tx = tid & 15;             // 0..15 -> col tile
    const int ty = tid >> 4;             // 0..15 -> row tile

    float acc[TM][TN];
    #pragma unroll
    for (int i = 0; i < TM; i++)
        #pragma unroll
        for (int j = 0; j < TN; j++) acc[i][j] = 0.f;

    float regM[TM], regN[TN];

    for (int k0 = 0; k0 < K; k0 += BKK) {
        #pragma unroll
        for (int off = 0; off < BM; off += 64) {
            float4 t = __ldg((const float4*)&A[(size_t)(rowBase + aRow + off) * K + k0 + aCol4]);
            As[aCol4 + 0][aRow + off] = t.x;
            As[aCol4 + 1][aRow + off] = t.y;
            As[aCol4 + 2][aRow + off] = t.z;
            As[aCol4 + 3][aRow + off] = t.w;
        }
        #pragma unroll
        for (int off = 0; off < BKK; off += 8) {
            *(float4*)&Bs[bRow + off][bCol4] =
                __ldg((const float4*)&Bm[(size_t)(k0 + bRow + off) * Nc + colBase + bCol4]);
        }
        __syncthreads();

        #pragma unroll
        for (int kk = 0; kk < BKK; kk++) {
            #pragma unroll
            for (int i = 0; i < TM; i += 4)
                *(float4*)&regM[i] = *(const float4*)&As[kk][ty * TM + i];
            #pragma unroll
            for (int j = 0; j < TN; j += 4)
                *(float4*)&regN[j] = *(const float4*)&Bs[kk][tx * TN + j];
            #pragma unroll
            for (int i = 0; i < TM; i++)
                #pragma unroll
                for (int j = 0; j < TN; j++)
                    acc[i][j] += regM[i] * regN[j];
        }
        __syncthreads();
    }

    #pragma unroll
    for (int i = 0; i < TM; i++) {
        const int row = rowBase + ty * TM + i;
        #pragma unroll
        for (int j = 0; j < TN; j += 4) {
            const int col = colBase + tx * TN + j;
            float4 o;
            o.x = acc[i][j + 0];
            o.y = acc[i][j + 1];
            o.z = acc[i][j + 2];
            o.w = acc[i][j + 3];
            if (bias) {
                o.x += bias[col + 0];
                o.y += bias[col + 1];
                o.z += bias[col + 2];
                o.w += bias[col + 3];
            }
            *(float4*)&C[(size_t)row * Nc + col] = o;
        }
    }
}

// ============================================================
// Sigma kernel: per (b, n), 8 warps -> 8 heads.
// inv = 1 / (exp(sigmoid(x . W_sigma[:,h] + b_sigma[h])) + 1)
// ============================================================
__global__ __launch_bounds__(256)
void sigma_kernel(const float* __restrict__ x, const float* __restrict__ Wsig,
                  const float* __restrict__ bsig, float* __restrict__ inv_out)
{
    const int bn = blockIdx.x;               // 0 .. B*N-1
    const int b = bn / N;
    const int n = bn % N;
    const int warp = threadIdx.x >> 5;       // head
    const int lane = threadIdx.x & 31;

    const float* xrow = x + (size_t)bn * D;
    float s = 0.f;
    #pragma unroll
    for (int it = 0; it < D / 128; it++) {   // 4 iterations, float4 each
        const int d = (lane + 32 * it) * 4;
        const float4 xv = __ldg((const float4*)&xrow[d]);
        s += xv.x * __ldg(&Wsig[(d + 0) * HEADS + warp]);
        s += xv.y * __ldg(&Wsig[(d + 1) * HEADS + warp]);
        s += xv.z * __ldg(&Wsig[(d + 2) * HEADS + warp]);
        s += xv.w * __ldg(&Wsig[(d + 3) * HEADS + warp]);
    }
    #pragma unroll
    for (int off = 16; off > 0; off >>= 1)
        s += __shfl_down_sync(0xFFFFFFFFu, s, off);

    if (lane == 0) {
        s += bsig[warp];
        float sig = 1.f / (1.f + expf(-s));
        float denom = expf(sig) + 1.f;
        inv_out[((size_t)b * HEADS + warp) * N + n] = 1.f / denom;
    }
}

// ============================================================
// Banded prior @ v.
// Grid: (32 i-tiles, 8 heads, 4 batches). 512 threads.
// smem: v rows [i0-BW, i0+RB+BW) x 64 dh, zero-padded OOB.
// out[i,:] = (1/Z_i) * sum_{|s|<=BW} r_i^{|s|} v[i+s,:]
// Z_i analytic (exact full-softmax normalizer, no truncation in Z).
// ============================================================
__global__ __launch_bounds__(512)
void band_kernel(const float* __restrict__ v, const float* __restrict__ inv_arr,
                 float* __restrict__ attn)
{
    __shared__ float vs[RB + 2 * BW][DH];   // 192 x 64 x 4B = 48KB

    const int b  = blockIdx.z;
    const int h  = blockIdx.y;
    const int i0 = blockIdx.x * RB;
    const int tid  = threadIdx.x;
    const int lane = tid & 63;               // dh component
    const int rg   = tid >> 6;               // 0..7

    // cooperative load, float4 granularity: (RB+2BW)*16 = 3072 float4
    for (int t = tid; t < (RB + 2 * BW) * (DH / 4); t += 512) {
        const int row = t >> 4;
        const int c4  = (t & 15) * 4;
        const int jj  = i0 - BW + row;
        float4 val = make_float4(0.f, 0.f, 0.f, 0.f);
        if (jj >= 0 && jj < N)
            val = __ldg((const float4*)&v[((size_t)(b * N + jj)) * INNER + h * DH + c4]);
        *(float4*)&vs[row][c4] = val;
    }
    __syncthreads();

    const float* invp = inv_arr + ((size_t)b * HEADS + h) * N;

    #pragma unroll
    for (int rr = 0; rr < RB / 8; rr++) {
        const int li = rg * 8 + rr;          // local row
        const int i  = i0 + li;
        const float inv = invp[i];
        const float r   = expf(-inv);

        float acc = vs[li + BW][lane];
        float w = r;
        #pragma unroll 4
        for (int s = 1; s <= BW; s++) {
            acc += w * (vs[li + BW - s][lane] + vs[li + BW + s][lane]);
            w *= r;
        }

        // exact normalizer: sum_{j=0}^{N-1} r^{|i-j|}
        const float Z = (1.f - expf(-(float)(i + 1) * inv)
                         + r  - expf(-(float)(N - i) * inv)) / (1.f - r);

        attn[((size_t)(b * N + i)) * INNER + h * DH + lane] = acc / Z;
    }
}

// ============================================================
// Launch
// Inputs (metadata order): x, W_v, W_sigma, b_sigma, W_out, b_out
// ============================================================
extern "C" void kernel_launch(void* const* d_in, const int* in_sizes, int n_in,
                              void* d_out, int out_size)
{
    const float* x      = (const float*)d_in[0];
    const float* W_v    = (const float*)d_in[1];
    const float* W_sig  = (const float*)d_in[2];
    const float* b_sig  = (const float*)d_in[3];
    const float* W_out  = (const float*)d_in[4];
    const float* b_out  = (const float*)d_in[5];
    float* out = (float*)d_out;

    float* v    = nullptr;
    float* attn = nullptr;
    float* inv  = nullptr;
    cudaGetSymbolAddress((void**)&v,    g_v);
    cudaGetSymbolAddress((void**)&attn, g_attn);
    cudaGetSymbolAddress((void**)&inv,  g_inv);

    const int M = B * N;   // 8192

    // v = x @ W_v
    {
        dim3 grid(INNER / BN, M / BM);
        sgemm_kernel<<<grid, 256>>>(x, W_v, nullptr, v, M, INNER, D);
    }
    // inv = 1/denom
    sigma_kernel<<<B * N, 256>>>(x, W_sig, b_sig, inv);
    // banded prior @ v
    {
        dim3 grid(N / RB, HEADS, B);
        band_kernel<<<grid, 512>>>(v, inv, attn);
    }
    // out = attn @ W_out + b_out
    {
        dim3 grid(D / BN, M / BM);
        sgemm_kernel<<<grid, 256>>>(attn, W_out, b_out, out, M, D, INNER);
    }
}

// round 3
// speedup vs baseline: 1.4154x; 1.4154x over previous
#include <cuda_runtime.h>
#include <cuda_bf16.h>
#include <math.h>
#include <stdint.h>

// Problem constants
#define B     4
#define N     2048
#define D     512
#define HEADS 8
#define DH    64
#define INNER 512
#define M_ROWS (B*N)        // 8192
#define KU512  (512/2)      // 256 u32 (bf16 pairs) per row of K=512

// Band params
#define BW 64
#define RB 64

// ---------------- scratch (__device__ globals; no allocation) ----------------
__device__ uint32_t g_xhi[M_ROWS * KU512];      // x split hi (bf16 pairs)
__device__ uint32_t g_xlo[M_ROWS * KU512];
__device__ uint32_t g_wvt_hi[INNER * KU512];    // W_v^T  [INNER][D/2]
__device__ uint32_t g_wvt_lo[INNER * KU512];
__device__ uint32_t g_wot_hi[D * (INNER/2)];    // W_out^T [D][INNER/2]
__device__ uint32_t g_wot_lo[D * (INNER/2)];
__device__ float    g_v[M_ROWS * INNER];        // v fp32
__device__ unsigned short g_ahi[M_ROWS * INNER];  // attn hi bf16
__device__ unsigned short g_alo[M_ROWS * INNER];  // attn lo bf16
__device__ float    g_inv[B*HEADS*N];

// ---------------- helpers ----------------
__device__ __forceinline__ uint32_t pack_bf16rn(float a, float b) {
    __nv_bfloat162 t = __floats2bfloat162_rn(a, b);   // .x = a (low half)
    return *reinterpret_cast<uint32_t*>(&t);
}

__device__ __forceinline__ void mma_bf16(float& d0, float& d1, float& d2, float& d3,
                                         uint32_t a0, uint32_t a1, uint32_t a2, uint32_t a3,
                                         uint32_t b0, uint32_t b1) {
    asm volatile(
        "mma.sync.aligned.m16n8k16.row.col.f32.bf16.bf16.f32 "
        "{%0,%1,%2,%3}, {%4,%5,%6,%7}, {%8,%9}, {%0,%1,%2,%3};\n"
        : "+f"(d0), "+f"(d1), "+f"(d2), "+f"(d3)
        : "r"(a0), "r"(a1), "r"(a2), "r"(a3), "r"(b0), "r"(b1));
}

// ============================================================
// convert_split: fp32 -> (hi bf16 = truncated top16, lo bf16 = rn(a - hi))
// packed as u32 pairs along the contiguous axis.
// ============================================================
__global__ __launch_bounds__(256)
void convert_split_kernel(const float4* __restrict__ in, uint2* __restrict__ hi,
                          uint2* __restrict__ lo, int n4)
{
    int i = blockIdx.x * blockDim.x + threadIdx.x;
    if (i >= n4) return;
    float4 v = in[i];
    uint32_t u0 = __float_as_uint(v.x), u1 = __float_as_uint(v.y);
    uint32_t u2 = __float_as_uint(v.z), u3 = __float_as_uint(v.w);
    uint2 H;
    H.x = __byte_perm(u0, u1, 0x7632);   // [v0_hi16 | v1_hi16], v0 in low half
    H.y = __byte_perm(u2, u3, 0x7632);
    float l0 = v.x - __uint_as_float(u0 & 0xFFFF0000u);
    float l1 = v.y - __uint_as_float(u1 & 0xFFFF0000u);
    float l2 = v.z - __uint_as_float(u2 & 0xFFFF0000u);
    float l3 = v.w - __uint_as_float(u3 & 0xFFFF0000u);
    uint2 L;
    L.x = pack_bf16rn(l0, l1);
    L.y = pack_bf16rn(l2, l3);
    hi[i] = H;
    lo[i] = L;
}

// ============================================================
// convert_wt: transpose W [K][Nc] fp32 -> Wt hi/lo [Nc][K/2] u32 (bf16 pairs along K)
// ============================================================
__global__ __launch_bounds__(256)
void convert_wt_kernel(const float* __restrict__ W, uint32_t* __restrict__ Whi,
                       uint32_t* __restrict__ Wlo, int K, int Nc)
{
    __shared__ float s[32][33];
    const int k0 = blockIdx.y * 32, n0 = blockIdx.x * 32;
    const int tx = threadIdx.x & 31, ty = threadIdx.x >> 5;  // ty 0..7
    #pragma unroll
    for (int q = 0; q < 4; q++)
        s[ty + 8*q][tx] = W[(size_t)(k0 + ty + 8*q) * Nc + n0 + tx];
    __syncthreads();
    for (int o = threadIdx.x; o < 512; o += 256) {
        const int n  = o >> 4;    // 0..31
        const int kp = o & 15;    // pair index within tile
        float v0 = s[2*kp][n], v1 = s[2*kp + 1][n];
        uint32_t w0 = __float_as_uint(v0), w1 = __float_as_uint(v1);
        uint32_t hi = __byte_perm(w0, w1, 0x7632);
        float l0 = v0 - __uint_as_float(w0 & 0xFFFF0000u);
        float l1 = v1 - __uint_as_float(w1 & 0xFFFF0000u);
        uint32_t lo = pack_bf16rn(l0, l1);
        size_t oi = (size_t)(n0 + n) * (K >> 1) + (k0 >> 1) + kp;
        Whi[oi] = hi;
        Wlo[oi] = lo;
    }
}

// ============================================================
// bf16x3 tensor-core GEMM: C[M][Nc] = A[M][K] @ Bt[Nc][K]^T (+bias)
// A,Bt given as hi/lo bf16 pairs (u32), C fp32.
// BM=BN=128, BK=32(16 u32), 256 threads / 8 warps, warp tile 64x32.
// ============================================================
__global__ __launch_bounds__(256, 2)
void gemm_bf16x3_kernel(const uint32_t* __restrict__ Ahi, const uint32_t* __restrict__ Alo,
                        const uint32_t* __restrict__ Bhi, const uint32_t* __restrict__ Blo,
                        const float* __restrict__ bias, float* __restrict__ C,
                        int Mrows, int Ncols, int K)
{
    const int KUr = K >> 1;  // u32 per row
    __shared__ uint32_t As_hi[128][20], As_lo[128][20];
    __shared__ uint32_t Bs_hi[128][20], Bs_lo[128][20];

    const int tid = threadIdx.x;
    const int wid = tid >> 5, lane = tid & 31;
    const int warp_m = wid & 1;        // 0..1 (64 rows each)
    const int warp_n = wid >> 1;       // 0..3 (32 cols each)
    const int r  = lane >> 2;          // 0..7
    const int cq = lane & 3;           // 0..3
    const int rowBase = blockIdx.y * 128;
    const int colBase = blockIdx.x * 128;

    float acc[4][4][4];
    #pragma unroll
    for (int a = 0; a < 4; a++)
        #pragma unroll
        for (int b_ = 0; b_ < 4; b_++)
            #pragma unroll
            for (int c = 0; c < 4; c++) acc[a][b_][c] = 0.f;

    const int cRow = tid >> 2;          // 0..63
    const int cQ4  = (tid & 3) * 4;     // 0,4,8,12

    for (int kt = 0; kt < KUr; kt += 16) {
        #pragma unroll
        for (int half = 0; half < 2; half++) {
            const int rr = cRow + half * 64;
            *(uint4*)&As_hi[rr][cQ4] = *(const uint4*)&Ahi[(size_t)(rowBase + rr) * KUr + kt + cQ4];
            *(uint4*)&As_lo[rr][cQ4] = *(const uint4*)&Alo[(size_t)(rowBase + rr) * KUr + kt + cQ4];
            *(uint4*)&Bs_hi[rr][cQ4] = *(const uint4*)&Bhi[(size_t)(colBase + rr) * KUr + kt + cQ4];
            *(uint4*)&Bs_lo[rr][cQ4] = *(const uint4*)&Blo[(size_t)(colBase + rr) * KUr + kt + cQ4];
        }
        __syncthreads();

        #pragma unroll
        for (int ks = 0; ks < 2; ks++) {
            const int ku = ks * 8;
            uint32_t bh[4][2], bl[4][2];
            #pragma unroll
            for (int nt = 0; nt < 4; nt++) {
                const int nb = warp_n * 32 + nt * 8;
                bh[nt][0] = Bs_hi[nb + r][ku + cq];
                bh[nt][1] = Bs_hi[nb + r][ku + cq + 4];
                bl[nt][0] = Bs_lo[nb + r][ku + cq];
                bl[nt][1] = Bs_lo[nb + r][ku + cq + 4];
            }
            #pragma unroll
            for (int mt = 0; mt < 4; mt++) {
                const int mb = warp_m * 64 + mt * 16;
                uint32_t ah0 = As_hi[mb + r][ku + cq];
                uint32_t ah1 = As_hi[mb + r + 8][ku + cq];
                uint32_t ah2 = As_hi[mb + r][ku + cq + 4];
                uint32_t ah3 = As_hi[mb + r + 8][ku + cq + 4];
                uint32_t al0 = As_lo[mb + r][ku + cq];
                uint32_t al1 = As_lo[mb + r + 8][ku + cq];
                uint32_t al2 = As_lo[mb + r][ku + cq + 4];
                uint32_t al3 = As_lo[mb + r + 8][ku + cq + 4];
                #pragma unroll
                for (int nt = 0; nt < 4; nt++) {
                    float* d = acc[mt][nt];
                    mma_bf16(d[0], d[1], d[2], d[3], al0, al1, al2, al3, bh[nt][0], bh[nt][1]);
                    mma_bf16(d[0], d[1], d[2], d[3], ah0, ah1, ah2, ah3, bl[nt][0], bl[nt][1]);
                    mma_bf16(d[0], d[1], d[2], d[3], ah0, ah1, ah2, ah3, bh[nt][0], bh[nt][1]);
                }
            }
        }
        __syncthreads();
    }

    // epilogue
    #pragma unroll
    for (int mt = 0; mt < 4; mt++) {
        const int row0 = rowBase + warp_m * 64 + mt * 16 + r;
        #pragma unroll
        for (int nt = 0; nt < 4; nt++) {
            const int col = colBase + warp_n * 32 + nt * 8 + 2 * cq;
            float b0v = 0.f, b1v = 0.f;
            if (bias) { b0v = bias[col]; b1v = bias[col + 1]; }
            float2 p0 = make_float2(acc[mt][nt][0] + b0v, acc[mt][nt][1] + b1v);
            float2 p1 = make_float2(acc[mt][nt][2] + b0v, acc[mt][nt][3] + b1v);
            *(float2*)&C[(size_t)row0 * Ncols + col]       = p0;
            *(float2*)&C[(size_t)(row0 + 8) * Ncols + col] = p1;
        }
    }
}

// ============================================================
// sigma: inv = 1/(exp(sigmoid(x.Wsig + b)) + 1) per (b,h,n)
// ============================================================
__global__ __launch_bounds__(256)
void sigma_kernel(const float* __restrict__ x, const float* __restrict__ Wsig,
                  const float* __restrict__ bsig, float* __restrict__ inv_out)
{
    const int bn = blockIdx.x;
    const int b = bn / N;
    const int n = bn % N;
    const int warp = threadIdx.x >> 5;
    const int lane = threadIdx.x & 31;

    const float* xrow = x + (size_t)bn * D;
    float s = 0.f;
    #pragma unroll
    for (int it = 0; it < D / 128; it++) {
        const int d = (lane + 32 * it) * 4;
        const float4 xv = __ldg((const float4*)&xrow[d]);
        s += xv.x * __ldg(&Wsig[(d + 0) * HEADS + warp]);
        s += xv.y * __ldg(&Wsig[(d + 1) * HEADS + warp]);
        s += xv.z * __ldg(&Wsig[(d + 2) * HEADS + warp]);
        s += xv.w * __ldg(&Wsig[(d + 3) * HEADS + warp]);
    }
    #pragma unroll
    for (int off = 16; off > 0; off >>= 1)
        s += __shfl_down_sync(0xFFFFFFFFu, s, off);

    if (lane == 0) {
        s += bsig[warp];
        float sig = 1.f / (1.f + expf(-s));
        float denom = expf(sig) + 1.f;
        inv_out[((size_t)b * HEADS + warp) * N + n] = 1.f / denom;
    }
}

// ============================================================
// Band kernel: 8 consecutive rows per thread, 1 LDS feeds 8 accumulators.
// Emits attn split (hi trunc bf16, lo rn bf16) directly.
// ============================================================
__global__ __launch_bounds__(512)
void band_kernel(const float* __restrict__ v, const float* __restrict__ inv_arr,
                 unsigned short* __restrict__ ahi, unsigned short* __restrict__ alo)
{
    __shared__ float vs[RB + 2 * BW][DH];   // 192 x 64 = 48KB

    const int b  = blockIdx.z;
    const int h  = blockIdx.y;
    const int i0 = blockIdx.x * RB;
    const int tid  = threadIdx.x;
    const int lane = tid & 63;
    const int g    = tid >> 6;              // 0..7

    for (int t = tid; t < (RB + 2 * BW) * (DH / 4); t += 512) {
        const int row = t >> 4;
        const int c4  = (t & 15) * 4;
        const int jj  = i0 - BW + row;
        float4 val = make_float4(0.f, 0.f, 0.f, 0.f);
        if (jj >= 0 && jj < N)
            val = __ldg((const float4*)&v[((size_t)(b * N + jj)) * INNER + h * DH + c4]);
        *(float4*)&vs[row][c4] = val;
    }
    __syncthreads();

    const float* invp = inv_arr + ((size_t)b * HEADS + h) * N;
    const int base = i0 + g * 8;

    float rr[8], iv[8], acc[8], w[8];
    #pragma unroll
    for (int t = 0; t < 8; t++) {
        iv[t]  = invp[base + t];
        rr[t]  = __expf(-iv[t]);
        acc[t] = 0.f;
    }

    // ---- Phase L: j descending, weight r^(i-j), center included ----
    #pragma unroll
    for (int t = 0; t < 8; t++) w[t] = __expf((float)(7 - t) * iv[t]);  // r^(t-7)
    {
        int jl = g * 8 + 71;
        #pragma unroll
        for (int m = 0; m < 8; m++) {             // entry peel, static masks
            const float val = vs[jl][lane];
            #pragma unroll
            for (int t = 0; t < 8; t++) {
                if (m + t >= 7) acc[t] += w[t] * val;
                w[t] *= rr[t];
            }
            jl--;
        }
        #pragma unroll 8
        for (int m = 8; m < 72; m++) {
            const float val = vs[jl][lane];
            #pragma unroll
            for (int t = 0; t < 8; t++) { acc[t] += w[t] * val; w[t] *= rr[t]; }
            jl--;
        }
    }

    // ---- Phase R: j ascending, weight r^(j-i), center excluded ----
    #pragma unroll
    for (int t = 0; t < 8; t++) w[t] = __expf((float)t * iv[t]);        // r^(-t)
    {
        int jl = g * 8 + 64;
        #pragma unroll
        for (int m = 0; m < 8; m++) {             // entry peel, static masks
            const float val = vs[jl][lane];
            #pragma unroll
            for (int t = 0; t < 8; t++) {
                if (m >= t + 1) acc[t] += w[t] * val;
                w[t] *= rr[t];
            }
            jl++;
        }
        #pragma unroll 8
        for (int m = 8; m < 72; m++) {
            const float val = vs[jl][lane];
            #pragma unroll
            for (int t = 0; t < 8; t++) { acc[t] += w[t] * val; w[t] *= rr[t]; }
            jl++;
        }
    }

    // ---- normalize (exact analytic Z) and emit bf16 hi/lo split ----
    #pragma unroll
    for (int t = 0; t < 8; t++) {
        const int i = base + t;
        const float r_ = rr[t];
        const float Z = (1.f - __expf(-(float)(i + 1) * iv[t])
                         + r_ - __expf(-(float)(N - i) * iv[t])) / (1.f - r_);
        const float o = acc[t] / Z;
        const uint32_t ob = __float_as_uint(o);
        const size_t idx = ((size_t)(b * N + i)) * INNER + h * DH + lane;
        ahi[idx] = (unsigned short)(ob >> 16);
        const float lof = o - __uint_as_float(ob & 0xFFFF0000u);
        __nv_bfloat16 lb = __float2bfloat16(lof);
        alo[idx] = *reinterpret_cast<unsigned short*>(&lb);
    }
}

// ============================================================
// Launch: x, W_v, W_sigma, b_sigma, W_out, b_out
// ============================================================
extern "C" void kernel_launch(void* const* d_in, const int* in_sizes, int n_in,
                              void* d_out, int out_size)
{
    const float* x     = (const float*)d_in[0];
    const float* W_v   = (const float*)d_in[1];
    const float* W_sig = (const float*)d_in[2];
    const float* b_sig = (const float*)d_in[3];
    const float* W_out = (const float*)d_in[4];
    const float* b_out = (const float*)d_in[5];
    float* out = (float*)d_out;

    uint32_t *xhi, *xlo, *wvt_hi, *wvt_lo, *wot_hi, *wot_lo;
    float *v, *inv;
    unsigned short *ahi, *alo;
    cudaGetSymbolAddress((void**)&xhi, g_xhi);
    cudaGetSymbolAddress((void**)&xlo, g_xlo);
    cudaGetSymbolAddress((void**)&wvt_hi, g_wvt_hi);
    cudaGetSymbolAddress((void**)&wvt_lo, g_wvt_lo);
    cudaGetSymbolAddress((void**)&wot_hi, g_wot_hi);
    cudaGetSymbolAddress((void**)&wot_lo, g_wot_lo);
    cudaGetSymbolAddress((void**)&v, g_v);
    cudaGetSymbolAddress((void**)&inv, g_inv);
    cudaGetSymbolAddress((void**)&ahi, g_ahi);
    cudaGetSymbolAddress((void**)&alo, g_alo);

    // split x into bf16 hi/lo
    {
        const int n4 = M_ROWS * D / 4;
        convert_split_kernel<<<n4 / 256, 256>>>((const float4*)x, (uint2*)xhi, (uint2*)xlo, n4);
    }
    // transpose+split weights
    {
        dim3 grid(INNER / 32, D / 32);
        convert_wt_kernel<<<grid, 256>>>(W_v, wvt_hi, wvt_lo, D, INNER);
    }
    {
        dim3 grid(D / 32, INNER / 32);
        convert_wt_kernel<<<grid, 256>>>(W_out, wot_hi, wot_lo, INNER, D);
    }
    // v = x @ W_v  (tensor core)
    {
        dim3 grid(INNER / 128, M_ROWS / 128);
        gemm_bf16x3_kernel<<<grid, 256>>>(xhi, xlo, wvt_hi, wvt_lo, nullptr, v,
                                          M_ROWS, INNER, D);
    }
    // sigma
    sigma_kernel<<<B * N, 256>>>(x, W_sig, b_sig, inv);
    // banded prior @ v  -> attn hi/lo
    {
        dim3 grid(N / RB, HEADS, B);
        band_kernel<<<grid, 512>>>(v, inv, ahi, alo);
    }
    // out = attn @ W_out + b_out  (tensor core)
    {
        dim3 grid(D / 128, M_ROWS / 128);
        gemm_bf16x3_kernel<<<grid, 256>>>((const uint32_t*)ahi, (const uint32_t*)alo,
                                          wot_hi, wot_lo, b_out, out,
                                          M_ROWS, D, INNER);
    }
}

// round 7
// speedup vs baseline: 2.3191x; 1.6385x over previous
#include <cuda_runtime.h>
#include <cuda_bf16.h>
#include <math.h>
#include <stdint.h>

// Problem constants
#define B     4
#define N     2048
#define D     512
#define HEADS 8
#define DH    64
#define INNER 512
#define M_ROWS (B*N)        // 8192
#define KU512  (512/2)      // 256 u32 (bf16 pairs) per row of K=512

// Band params
#define BW 64
#define RB 64

// GEMM smem geometry (u32 units)
#define ROWSTRIDE 20                    // 16 payload + 4 pad (conflict-free)
#define ARR_U32   (128 * ROWSTRIDE)     // 2560 u32 per array
#define STAGE_U32 (4 * ARR_U32)         // 10240 u32 = 40KB per stage
#define GEMM_SMEM_BYTES (2 * STAGE_U32 * 4)  // 81920

// ---------------- scratch (__device__ globals; no allocation) ----------------
__device__ uint32_t g_xhi[M_ROWS * KU512];
__device__ uint32_t g_xlo[M_ROWS * KU512];
__device__ uint32_t g_wvt_hi[INNER * KU512];
__device__ uint32_t g_wvt_lo[INNER * KU512];
__device__ uint32_t g_wot_hi[D * (INNER/2)];
__device__ uint32_t g_wot_lo[D * (INNER/2)];
__device__ float    g_v[M_ROWS * INNER];
__device__ unsigned short g_ahi[M_ROWS * INNER];
__device__ unsigned short g_alo[M_ROWS * INNER];
__device__ float    g_inv[B*HEADS*N];

// ---------------- helpers ----------------
__device__ __forceinline__ uint32_t pack_bf16rn(float a, float b) {
    __nv_bfloat162 t = __floats2bfloat162_rn(a, b);
    return *reinterpret_cast<uint32_t*>(&t);
}

__device__ __forceinline__ void mma_bf16(float& d0, float& d1, float& d2, float& d3,
                                         uint32_t a0, uint32_t a1, uint32_t a2, uint32_t a3,
                                         uint32_t b0, uint32_t b1) {
    asm volatile(
        "mma.sync.aligned.m16n8k16.row.col.f32.bf16.bf16.f32 "
        "{%0,%1,%2,%3}, {%4,%5,%6,%7}, {%8,%9}, {%0,%1,%2,%3};\n"
        : "+f"(d0), "+f"(d1), "+f"(d2), "+f"(d3)
        : "r"(a0), "r"(a1), "r"(a2), "r"(a3), "r"(b0), "r"(b1));
}

__device__ __forceinline__ void cp_async16(uint32_t* smem, const uint32_t* gmem) {
    uint32_t s = (uint32_t)__cvta_generic_to_shared(smem);
    asm volatile("cp.async.cg.shared.global [%0], [%1], 16;\n" :: "r"(s), "l"(gmem));
}
__device__ __forceinline__ void cp_commit() { asm volatile("cp.async.commit_group;\n"); }
__device__ __forceinline__ void cp_wait1()  { asm volatile("cp.async.wait_group 1;\n"); }
__device__ __forceinline__ void cp_wait0()  { asm volatile("cp.async.wait_group 0;\n"); }

// ============================================================
// convert_split: fp32 -> (hi bf16 trunc, lo bf16 rn(a-hi)), packed pairs
// ============================================================
__global__ __launch_bounds__(256)
void convert_split_kernel(const float4* __restrict__ in, uint2* __restrict__ hi,
                          uint2* __restrict__ lo, int n4)
{
    int i = blockIdx.x * blockDim.x + threadIdx.x;
    if (i >= n4) return;
    float4 v = in[i];
    uint32_t u0 = __float_as_uint(v.x), u1 = __float_as_uint(v.y);
    uint32_t u2 = __float_as_uint(v.z), u3 = __float_as_uint(v.w);
    uint2 H;
    H.x = __byte_perm(u0, u1, 0x7632);
    H.y = __byte_perm(u2, u3, 0x7632);
    float l0 = v.x - __uint_as_float(u0 & 0xFFFF0000u);
    float l1 = v.y - __uint_as_float(u1 & 0xFFFF0000u);
    float l2 = v.z - __uint_as_float(u2 & 0xFFFF0000u);
    float l3 = v.w - __uint_as_float(u3 & 0xFFFF0000u);
    uint2 L;
    L.x = pack_bf16rn(l0, l1);
    L.y = pack_bf16rn(l2, l3);
    hi[i] = H;
    lo[i] = L;
}

// ============================================================
// convert_wt: transpose W [K][Nc] fp32 -> Wt hi/lo [Nc][K/2] u32
// ============================================================
__global__ __launch_bounds__(256)
void convert_wt_kernel(const float* __restrict__ W, uint32_t* __restrict__ Whi,
                       uint32_t* __restrict__ Wlo, int K, int Nc)
{
    __shared__ float s[32][33];
    const int k0 = blockIdx.y * 32, n0 = blockIdx.x * 32;
    const int tx = threadIdx.x & 31, ty = threadIdx.x >> 5;
    #pragma unroll
    for (int q = 0; q < 4; q++)
        s[ty + 8*q][tx] = W[(size_t)(k0 + ty + 8*q) * Nc + n0 + tx];
    __syncthreads();
    for (int o = threadIdx.x; o < 512; o += 256) {
        const int n  = o >> 4;
        const int kp = o & 15;
        float v0 = s[2*kp][n], v1 = s[2*kp + 1][n];
        uint32_t w0 = __float_as_uint(v0), w1 = __float_as_uint(v1);
        uint32_t hi = __byte_perm(w0, w1, 0x7632);
        float l0 = v0 - __uint_as_float(w0 & 0xFFFF0000u);
        float l1 = v1 - __uint_as_float(w1 & 0xFFFF0000u);
        uint32_t lo = pack_bf16rn(l0, l1);
        size_t oi = (size_t)(n0 + n) * (K >> 1) + (k0 >> 1) + kp;
        Whi[oi] = hi;
        Wlo[oi] = lo;
    }
}

// ============================================================
// bf16x3 tensor GEMM with 2-stage cp.async double-buffer pipeline.
// Dynamic smem: 2 stages x {As_hi,As_lo,Bs_hi,Bs_lo}[128][20] = 80KB.
// ============================================================
__global__ __launch_bounds__(256)
void gemm_bf16x3_kernel(const uint32_t* __restrict__ Ahi, const uint32_t* __restrict__ Alo,
                        const uint32_t* __restrict__ Bhi, const uint32_t* __restrict__ Blo,
                        const float* __restrict__ bias, float* __restrict__ C,
                        int Mrows, int Ncols, int K)
{
    extern __shared__ uint32_t smem[];
    const int KUr = K >> 1;
    const int ntiles = KUr >> 4;

    const int tid = threadIdx.x;
    const int wid = tid >> 5, lane = tid & 31;
    const int warp_m = wid & 1;
    const int warp_n = wid >> 1;
    const int r  = lane >> 2;
    const int cq = lane & 3;
    const int rowBase = blockIdx.y * 128;
    const int colBase = blockIdx.x * 128;

    const int cRow = tid >> 2;          // 0..63
    const int cQ4  = (tid & 3) * 4;     // 0,4,8,12

    // prefetch lambda-ish macro: tile kt -> stage st
    #define PREFETCH(kt, st) do {                                                     \
        uint32_t* s_ = smem + (st) * STAGE_U32;                                       \
        _Pragma("unroll")                                                             \
        for (int half = 0; half < 2; half++) {                                        \
            const int rr_ = cRow + half * 64;                                         \
            const size_t ao_ = (size_t)(rowBase + rr_) * KUr + (kt) + cQ4;            \
            const size_t bo_ = (size_t)(colBase + rr_) * KUr + (kt) + cQ4;            \
            cp_async16(s_ + 0*ARR_U32 + rr_*ROWSTRIDE + cQ4, Ahi + ao_);              \
            cp_async16(s_ + 1*ARR_U32 + rr_*ROWSTRIDE + cQ4, Alo + ao_);              \
            cp_async16(s_ + 2*ARR_U32 + rr_*ROWSTRIDE + cQ4, Bhi + bo_);              \
            cp_async16(s_ + 3*ARR_U32 + rr_*ROWSTRIDE + cQ4, Blo + bo_);              \
        }                                                                             \
    } while (0)

    float acc[4][4][4];
    #pragma unroll
    for (int a = 0; a < 4; a++)
        #pragma unroll
        for (int b_ = 0; b_ < 4; b_++)
            #pragma unroll
            for (int c = 0; c < 4; c++) acc[a][b_][c] = 0.f;

    PREFETCH(0, 0);
    cp_commit();

    for (int t = 0; t < ntiles; t++) {
        if (t + 1 < ntiles) {
            PREFETCH((t + 1) * 16, (t + 1) & 1);
            cp_commit();
            cp_wait1();
        } else {
            cp_wait0();
        }
        __syncthreads();

        const uint32_t* As_hi = smem + (t & 1) * STAGE_U32 + 0 * ARR_U32;
        const uint32_t* As_lo = smem + (t & 1) * STAGE_U32 + 1 * ARR_U32;
        const uint32_t* Bs_hi = smem + (t & 1) * STAGE_U32 + 2 * ARR_U32;
        const uint32_t* Bs_lo = smem + (t & 1) * STAGE_U32 + 3 * ARR_U32;

        #pragma unroll
        for (int ks = 0; ks < 2; ks++) {
            const int ku = ks * 8;
            uint32_t bh[4][2], bl[4][2];
            #pragma unroll
            for (int nt = 0; nt < 4; nt++) {
                const int nb = warp_n * 32 + nt * 8;
                bh[nt][0] = Bs_hi[(nb + r) * ROWSTRIDE + ku + cq];
                bh[nt][1] = Bs_hi[(nb + r) * ROWSTRIDE + ku + cq + 4];
                bl[nt][0] = Bs_lo[(nb + r) * ROWSTRIDE + ku + cq];
                bl[nt][1] = Bs_lo[(nb + r) * ROWSTRIDE + ku + cq + 4];
            }
            #pragma unroll
            for (int mt = 0; mt < 4; mt++) {
                const int mb = warp_m * 64 + mt * 16;
                uint32_t ah0 = As_hi[(mb + r) * ROWSTRIDE + ku + cq];
                uint32_t ah1 = As_hi[(mb + r + 8) * ROWSTRIDE + ku + cq];
                uint32_t ah2 = As_hi[(mb + r) * ROWSTRIDE + ku + cq + 4];
                uint32_t ah3 = As_hi[(mb + r + 8) * ROWSTRIDE + ku + cq + 4];
                uint32_t al0 = As_lo[(mb + r) * ROWSTRIDE + ku + cq];
                uint32_t al1 = As_lo[(mb + r + 8) * ROWSTRIDE + ku + cq];
                uint32_t al2 = As_lo[(mb + r) * ROWSTRIDE + ku + cq + 4];
                uint32_t al3 = As_lo[(mb + r + 8) * ROWSTRIDE + ku + cq + 4];
                #pragma unroll
                for (int nt = 0; nt < 4; nt++) {
                    float* d = acc[mt][nt];
                    mma_bf16(d[0], d[1], d[2], d[3], al0, al1, al2, al3, bh[nt][0], bh[nt][1]);
                    mma_bf16(d[0], d[1], d[2], d[3], ah0, ah1, ah2, ah3, bl[nt][0], bl[nt][1]);
                    mma_bf16(d[0], d[1], d[2], d[3], ah0, ah1, ah2, ah3, bh[nt][0], bh[nt][1]);
                }
            }
        }
        __syncthreads();
    }
    #undef PREFETCH

    #pragma unroll
    for (int mt = 0; mt < 4; mt++) {
        const int row0 = rowBase + warp_m * 64 + mt * 16 + r;
        #pragma unroll
        for (int nt = 0; nt < 4; nt++) {
            const int col = colBase + warp_n * 32 + nt * 8 + 2 * cq;
            float b0v = 0.f, b1v = 0.f;
            if (bias) { b0v = bias[col]; b1v = bias[col + 1]; }
            float2 p0 = make_float2(acc[mt][nt][0] + b0v, acc[mt][nt][1] + b1v);
            float2 p1 = make_float2(acc[mt][nt][2] + b0v, acc[mt][nt][3] + b1v);
            *(float2*)&C[(size_t)row0 * Ncols + col]       = p0;
            *(float2*)&C[(size_t)(row0 + 8) * Ncols + col] = p1;
        }
    }
}

// ============================================================
// sigma: one warp per (b,n); each THREAD accumulates all 8 heads,
// Wsig reads fully coalesced (2x float4 per lane = 1KB/warp).
// ============================================================
__global__ __launch_bounds__(256)
void sigma_kernel(const float* __restrict__ x, const float4* __restrict__ Wsig,
                  const float* __restrict__ bsig, float* __restrict__ inv_out)
{
    const int warp = threadIdx.x >> 5;
    const int lane = threadIdx.x & 31;
    const int bn = blockIdx.x * 8 + warp;
    const int b = bn / N;
    const int n = bn % N;

    const float* xrow = x + (size_t)bn * D;
    float acc[HEADS];
    #pragma unroll
    for (int h = 0; h < HEADS; h++) acc[h] = 0.f;

    #pragma unroll
    for (int it = 0; it < D / 32; it++) {
        const int d = lane + 32 * it;
        const float xv = __ldg(&xrow[d]);
        const float4 w0 = __ldg(&Wsig[d * 2 + 0]);
        const float4 w1 = __ldg(&Wsig[d * 2 + 1]);
        acc[0] += xv * w0.x;  acc[1] += xv * w0.y;
        acc[2] += xv * w0.z;  acc[3] += xv * w0.w;
        acc[4] += xv * w1.x;  acc[5] += xv * w1.y;
        acc[6] += xv * w1.z;  acc[7] += xv * w1.w;
    }

    #pragma unroll
    for (int off = 16; off > 0; off >>= 1)
        #pragma unroll
        for (int h = 0; h < HEADS; h++)
            acc[h] += __shfl_xor_sync(0xFFFFFFFFu, acc[h], off);

    if (lane < HEADS) {
        const int h = lane;
        float s = acc[h] + __ldg(&bsig[h]);
        float sig = 1.f / (1.f + expf(-s));
        float denom = expf(sig) + 1.f;
        inv_out[((size_t)b * HEADS + h) * N + n] = 1.f / denom;
    }
}

// ============================================================
// Band kernel (proven in round 3): 8 consecutive rows/thread,
// geometric running weights, exact analytic Z, bf16 hi/lo emit.
// ============================================================
__global__ __launch_bounds__(512)
void band_kernel(const float* __restrict__ v, const float* __restrict__ inv_arr,
                 unsigned short* __restrict__ ahi, unsigned short* __restrict__ alo)
{
    __shared__ float vs[RB + 2 * BW][DH];   // 48KB

    const int b  = blockIdx.z;
    const int h  = blockIdx.y;
    const int i0 = blockIdx.x * RB;
    const int tid  = threadIdx.x;
    const int lane = tid & 63;
    const int g    = tid >> 6;

    for (int t = tid; t < (RB + 2 * BW) * (DH / 4); t += 512) {
        const int row = t >> 4;
        const int c4  = (t & 15) * 4;
        const int jj  = i0 - BW + row;
        float4 val = make_float4(0.f, 0.f, 0.f, 0.f);
        if (jj >= 0 && jj < N)
            val = __ldg((const float4*)&v[((size_t)(b * N + jj)) * INNER + h * DH + c4]);
        *(float4*)&vs[row][c4] = val;
    }
    __syncthreads();

    const float* invp = inv_arr + ((size_t)b * HEADS + h) * N;
    const int base = i0 + g * 8;

    float rr[8], iv[8], acc[8], w[8];
    #pragma unroll
    for (int t = 0; t < 8; t++) {
        iv[t]  = invp[base + t];
        rr[t]  = __expf(-iv[t]);
        acc[t] = 0.f;
    }

    #pragma unroll
    for (int t = 0; t < 8; t++) w[t] = __expf((float)(7 - t) * iv[t]);
    {
        int jl = g * 8 + 71;
        #pragma unroll
        for (int m = 0; m < 8; m++) {
            const float val = vs[jl][lane];
            #pragma unroll
            for (int t = 0; t < 8; t++) {
                if (m + t >= 7) acc[t] += w[t] * val;
                w[t] *= rr[t];
            }
            jl--;
        }
        #pragma unroll 8
        for (int m = 8; m < 72; m++) {
            const float val = vs[jl][lane];
            #pragma unroll
            for (int t = 0; t < 8; t++) { acc[t] += w[t] * val; w[t] *= rr[t]; }
            jl--;
        }
    }

    #pragma unroll
    for (int t = 0; t < 8; t++) w[t] = __expf((float)t * iv[t]);
    {
        int jl = g * 8 + 64;
        #pragma unroll
        for (int m = 0; m < 8; m++) {
            const float val = vs[jl][lane];
            #pragma unroll
            for (int t = 0; t < 8; t++) {
                if (m >= t + 1) acc[t] += w[t] * val;
                w[t] *= rr[t];
            }
            jl++;
        }
        #pragma unroll 8
        for (int m = 8; m < 72; m++) {
            const float val = vs[jl][lane];
            #pragma unroll
            for (int t = 0; t < 8; t++) { acc[t] += w[t] * val; w[t] *= rr[t]; }
            jl++;
        }
    }

    #pragma unroll
    for (int t = 0; t < 8; t++) {
        const int i = base + t;
        const float r_ = rr[t];
        const float Z = (1.f - __expf(-(float)(i + 1) * iv[t])
                         + r_ - __expf(-(float)(N - i) * iv[t])) / (1.f - r_);
        const float o = acc[t] / Z;
        const uint32_t ob = __float_as_uint(o);
        const size_t idx = ((size_t)(b * N + i)) * INNER + h * DH + lane;
        ahi[idx] = (unsigned short)(ob >> 16);
        const float lof = o - __uint_as_float(ob & 0xFFFF0000u);
        __nv_bfloat16 lb = __float2bfloat16(lof);
        alo[idx] = *reinterpret_cast<unsigned short*>(&lb);
    }
}

// ============================================================
// Launch: x, W_v, W_sigma, b_sigma, W_out, b_out
// ============================================================
extern "C" void kernel_launch(void* const* d_in, const int* in_sizes, int n_in,
                              void* d_out, int out_size)
{
    const float* x     = (const float*)d_in[0];
    const float* W_v   = (const float*)d_in[1];
    const float* W_sig = (const float*)d_in[2];
    const float* b_sig = (const float*)d_in[3];
    const float* W_out = (const float*)d_in[4];
    const float* b_out = (const float*)d_in[5];
    float* out = (float*)d_out;

    uint32_t *xhi, *xlo, *wvt_hi, *wvt_lo, *wot_hi, *wot_lo;
    float *v, *inv;
    unsigned short *ahi, *alo;
    cudaGetSymbolAddress((void**)&xhi, g_xhi);
    cudaGetSymbolAddress((void**)&xlo, g_xlo);
    cudaGetSymbolAddress((void**)&wvt_hi, g_wvt_hi);
    cudaGetSymbolAddress((void**)&wvt_lo, g_wvt_lo);
    cudaGetSymbolAddress((void**)&wot_hi, g_wot_hi);
    cudaGetSymbolAddress((void**)&wot_lo, g_wot_lo);
    cudaGetSymbolAddress((void**)&v, g_v);
    cudaGetSymbolAddress((void**)&inv, g_inv);
    cudaGetSymbolAddress((void**)&ahi, g_ahi);
    cudaGetSymbolAddress((void**)&alo, g_alo);

    static bool attr_set = false;
    if (!attr_set) {
        cudaFuncSetAttribute(gemm_bf16x3_kernel,
                             cudaFuncAttributeMaxDynamicSharedMemorySize,
                             GEMM_SMEM_BYTES);
        attr_set = true;
    }

    // split x into bf16 hi/lo
    {
        const int n4 = M_ROWS * D / 4;
        convert_split_kernel<<<n4 / 256, 256>>>((const float4*)x, (uint2*)xhi, (uint2*)xlo, n4);
    }
    // transpose+split weights
    {
        dim3 grid(INNER / 32, D / 32);
        convert_wt_kernel<<<grid, 256>>>(W_v, wvt_hi, wvt_lo, D, INNER);
    }
    {
        dim3 grid(D / 32, INNER / 32);
        convert_wt_kernel<<<grid, 256>>>(W_out, wot_hi, wot_lo, INNER, D);
    }
    // v = x @ W_v
    {
        dim3 grid(INNER / 128, M_ROWS / 128);
        gemm_bf16x3_kernel<<<grid, 256, GEMM_SMEM_BYTES>>>(xhi, xlo, wvt_hi, wvt_lo,
                                                           nullptr, v, M_ROWS, INNER, D);
    }
    // sigma
    sigma_kernel<<<M_ROWS / 8, 256>>>(x, (const float4*)W_sig, b_sig, inv);
    // banded prior @ v -> attn hi/lo
    {
        dim3 grid(N / RB, HEADS, B);
        band_kernel<<<grid, 512>>>(v, inv, ahi, alo);
    }
    // out = attn @ W_out + b_out
    {
        dim3 grid(D / 128, M_ROWS / 128);
        gemm_bf16x3_kernel<<<grid, 256, GEMM_SMEM_BYTES>>>((const uint32_t*)ahi,
                                                           (const uint32_t*)alo,
                                                           wot_hi, wot_lo, b_out, out,
                                                           M_ROWS, D, INNER);
    }
}

// round 8
// speedup vs baseline: 2.5096x; 1.0821x over previous
#include <cuda_runtime.h>
#include <cuda_bf16.h>
#include <math.h>
#include <stdint.h>

// Problem constants
#define B     4
#define N     2048
#define D     512
#define HEADS 8
#define DH    64
#define INNER 512
#define M_ROWS (B*N)        // 8192
#define KU512  (512/2)      // 256 u32 (bf16 pairs) per row of K=512

// Band params
#define BW 64
#define RB 64

// GEMM smem geometry (u32 units)
#define ROWSTRIDE 20                    // 16 payload + 4 pad (conflict-free, incl. ldmatrix)
#define ARR_U32   (128 * ROWSTRIDE)     // 2560 u32 per array
#define STAGE_U32 (4 * ARR_U32)         // 10240 u32 = 40KB per stage
#define GEMM_SMEM_BYTES (2 * STAGE_U32 * 4)  // 81920

// ---------------- scratch (__device__ globals; no allocation) ----------------
__device__ uint32_t g_xhi[M_ROWS * KU512];
__device__ uint32_t g_xlo[M_ROWS * KU512];
__device__ uint32_t g_wvt_hi[INNER * KU512];
__device__ uint32_t g_wvt_lo[INNER * KU512];
__device__ uint32_t g_wot_hi[D * (INNER/2)];
__device__ uint32_t g_wot_lo[D * (INNER/2)];
__device__ float    g_v[M_ROWS * INNER];
__device__ unsigned short g_ahi[M_ROWS * INNER];
__device__ unsigned short g_alo[M_ROWS * INNER];
__device__ float    g_inv[B*HEADS*N];

// ---------------- helpers ----------------
__device__ __forceinline__ uint32_t pack_bf16rn(float a, float b) {
    __nv_bfloat162 t = __floats2bfloat162_rn(a, b);
    return *reinterpret_cast<uint32_t*>(&t);
}

__device__ __forceinline__ void mma_bf16(float& d0, float& d1, float& d2, float& d3,
                                         uint32_t a0, uint32_t a1, uint32_t a2, uint32_t a3,
                                         uint32_t b0, uint32_t b1) {
    asm volatile(
        "mma.sync.aligned.m16n8k16.row.col.f32.bf16.bf16.f32 "
        "{%0,%1,%2,%3}, {%4,%5,%6,%7}, {%8,%9}, {%0,%1,%2,%3};\n"
        : "+f"(d0), "+f"(d1), "+f"(d2), "+f"(d3)
        : "r"(a0), "r"(a1), "r"(a2), "r"(a3), "r"(b0), "r"(b1));
}

__device__ __forceinline__ void ldsm_x4(uint32_t& r0, uint32_t& r1, uint32_t& r2, uint32_t& r3,
                                        uint32_t addr) {
    asm volatile("ldmatrix.sync.aligned.m8n8.x4.shared.b16 {%0,%1,%2,%3}, [%4];\n"
                 : "=r"(r0), "=r"(r1), "=r"(r2), "=r"(r3) : "r"(addr));
}

__device__ __forceinline__ void cp_async16(uint32_t* smem, const uint32_t* gmem) {
    uint32_t s = (uint32_t)__cvta_generic_to_shared(smem);
    asm volatile("cp.async.cg.shared.global [%0], [%1], 16;\n" :: "r"(s), "l"(gmem));
}
__device__ __forceinline__ void cp_commit() { asm volatile("cp.async.commit_group;\n"); }
__device__ __forceinline__ void cp_wait1()  { asm volatile("cp.async.wait_group 1;\n"); }
__device__ __forceinline__ void cp_wait0()  { asm volatile("cp.async.wait_group 0;\n"); }

// ============================================================
// convert_split: fp32 -> (hi bf16 trunc, lo bf16 rn(a-hi)), packed pairs
// ============================================================
__global__ __launch_bounds__(256)
void convert_split_kernel(const float4* __restrict__ in, uint2* __restrict__ hi,
                          uint2* __restrict__ lo, int n4)
{
    int i = blockIdx.x * blockDim.x + threadIdx.x;
    if (i >= n4) return;
    float4 v = in[i];
    uint32_t u0 = __float_as_uint(v.x), u1 = __float_as_uint(v.y);
    uint32_t u2 = __float_as_uint(v.z), u3 = __float_as_uint(v.w);
    uint2 H;
    H.x = __byte_perm(u0, u1, 0x7632);
    H.y = __byte_perm(u2, u3, 0x7632);
    float l0 = v.x - __uint_as_float(u0 & 0xFFFF0000u);
    float l1 = v.y - __uint_as_float(u1 & 0xFFFF0000u);
    float l2 = v.z - __uint_as_float(u2 & 0xFFFF0000u);
    float l3 = v.w - __uint_as_float(u3 & 0xFFFF0000u);
    uint2 L;
    L.x = pack_bf16rn(l0, l1);
    L.y = pack_bf16rn(l2, l3);
    hi[i] = H;
    lo[i] = L;
}

// ============================================================
// convert_wt: transpose W [K][Nc] fp32 -> Wt hi/lo [Nc][K/2] u32
// ============================================================
__global__ __launch_bounds__(256)
void convert_wt_kernel(const float* __restrict__ W, uint32_t* __restrict__ Whi,
                       uint32_t* __restrict__ Wlo, int K, int Nc)
{
    __shared__ float s[32][33];
    const int k0 = blockIdx.y * 32, n0 = blockIdx.x * 32;
    const int tx = threadIdx.x & 31, ty = threadIdx.x >> 5;
    #pragma unroll
    for (int q = 0; q < 4; q++)
        s[ty + 8*q][tx] = W[(size_t)(k0 + ty + 8*q) * Nc + n0 + tx];
    __syncthreads();
    for (int o = threadIdx.x; o < 512; o += 256) {
        const int n  = o >> 4;
        const int kp = o & 15;
        float v0 = s[2*kp][n], v1 = s[2*kp + 1][n];
        uint32_t w0 = __float_as_uint(v0), w1 = __float_as_uint(v1);
        uint32_t hi = __byte_perm(w0, w1, 0x7632);
        float l0 = v0 - __uint_as_float(w0 & 0xFFFF0000u);
        float l1 = v1 - __uint_as_float(w1 & 0xFFFF0000u);
        uint32_t lo = pack_bf16rn(l0, l1);
        size_t oi = (size_t)(n0 + n) * (K >> 1) + (k0 >> 1) + kp;
        Whi[oi] = hi;
        Wlo[oi] = lo;
    }
}

// ============================================================
// bf16x3 tensor GEMM: 2-stage cp.async pipeline + ldmatrix fragment loads.
// Dynamic smem: 2 stages x {As_hi,As_lo,Bs_hi,Bs_lo}[128][20] = 80KB.
// ============================================================
__global__ __launch_bounds__(256, 2)
void gemm_bf16x3_kernel(const uint32_t* __restrict__ Ahi, const uint32_t* __restrict__ Alo,
                        const uint32_t* __restrict__ Bhi, const uint32_t* __restrict__ Blo,
                        const float* __restrict__ bias, float* __restrict__ C,
                        int Mrows, int Ncols, int K)
{
    extern __shared__ uint32_t smem[];
    const int KUr = K >> 1;
    const int ntiles = KUr >> 4;

    const int tid = threadIdx.x;
    const int wid = tid >> 5, lane = tid & 31;
    const int warp_m = wid & 1;
    const int warp_n = wid >> 1;
    const int r  = lane >> 2;
    const int cq = lane & 3;
    const int rowBase = blockIdx.y * 128;
    const int colBase = blockIdx.x * 128;

    const int cRow = tid >> 2;          // 0..63
    const int cQ4  = (tid & 3) * 4;     // 0,4,8,12

    // ldmatrix per-lane offsets (u32 units), relative to array base + ku
    // A (16x16 fragment, 4 matrices): rows mt*16+(lane&15), k-half by lane>>4
    const int aOffBase = (warp_m * 64 + (lane & 15)) * ROWSTRIDE + ((lane >> 4) << 2);
    // B (two n-octets x k-halves): row nb+(lane&7)+((lane>>4)<<3), k-half by (lane>>3)&1
    const int bOffBase = (warp_n * 32 + (lane & 7) + ((lane >> 4) << 3)) * ROWSTRIDE
                         + (((lane >> 3) & 1) << 2);

    const uint32_t smem_base_addr = (uint32_t)__cvta_generic_to_shared(smem);

    #define PREFETCH(kt, st) do {                                                     \
        uint32_t* s_ = smem + (st) * STAGE_U32;                                       \
        _Pragma("unroll")                                                             \
        for (int half = 0; half < 2; half++) {                                        \
            const int rr_ = cRow + half * 64;                                         \
            const size_t ao_ = (size_t)(rowBase + rr_) * KUr + (kt) + cQ4;            \
            const size_t bo_ = (size_t)(colBase + rr_) * KUr + (kt) + cQ4;            \
            cp_async16(s_ + 0*ARR_U32 + rr_*ROWSTRIDE + cQ4, Ahi + ao_);              \
            cp_async16(s_ + 1*ARR_U32 + rr_*ROWSTRIDE + cQ4, Alo + ao_);              \
            cp_async16(s_ + 2*ARR_U32 + rr_*ROWSTRIDE + cQ4, Bhi + bo_);              \
            cp_async16(s_ + 3*ARR_U32 + rr_*ROWSTRIDE + cQ4, Blo + bo_);              \
        }                                                                             \
    } while (0)

    float acc[4][4][4];
    #pragma unroll
    for (int a = 0; a < 4; a++)
        #pragma unroll
        for (int b_ = 0; b_ < 4; b_++)
            #pragma unroll
            for (int c = 0; c < 4; c++) acc[a][b_][c] = 0.f;

    PREFETCH(0, 0);
    cp_commit();

    for (int t = 0; t < ntiles; t++) {
        if (t + 1 < ntiles) {
            PREFETCH((t + 1) * 16, (t + 1) & 1);
            cp_commit();
            cp_wait1();
        } else {
            cp_wait0();
        }
        __syncthreads();

        const uint32_t stage = smem_base_addr + ((t & 1) * STAGE_U32) * 4;
        const uint32_t aHiB = stage + (0 * ARR_U32 + aOffBase) * 4;
        const uint32_t aLoB = stage + (1 * ARR_U32 + aOffBase) * 4;
        const uint32_t bHiB = stage + (2 * ARR_U32 + bOffBase) * 4;
        const uint32_t bLoB = stage + (3 * ARR_U32 + bOffBase) * 4;

        #pragma unroll
        for (int ks = 0; ks < 2; ks++) {
            const uint32_t kuB = ks * 8 * 4;   // byte offset of k-subtile
            // B fragments: 2 ldmatrix.x4 per precision (each covers 2 n-octets)
            uint32_t bh[4][2], bl[4][2];
            #pragma unroll
            for (int pair = 0; pair < 2; pair++) {
                const uint32_t po = pair * 16 * ROWSTRIDE * 4;
                ldsm_x4(bh[2*pair][0], bh[2*pair][1], bh[2*pair+1][0], bh[2*pair+1][1],
                        bHiB + po + kuB);
                ldsm_x4(bl[2*pair][0], bl[2*pair][1], bl[2*pair+1][0], bl[2*pair+1][1],
                        bLoB + po + kuB);
            }
            #pragma unroll
            for (int mt = 0; mt < 4; mt++) {
                const uint32_t mo = mt * 16 * ROWSTRIDE * 4;
                uint32_t ah0, ah1, ah2, ah3, al0, al1, al2, al3;
                ldsm_x4(ah0, ah1, ah2, ah3, aHiB + mo + kuB);
                ldsm_x4(al0, al1, al2, al3, aLoB + mo + kuB);
                #pragma unroll
                for (int nt = 0; nt < 4; nt++) {
                    float* d = acc[mt][nt];
                    mma_bf16(d[0], d[1], d[2], d[3], al0, al1, al2, al3, bh[nt][0], bh[nt][1]);
                    mma_bf16(d[0], d[1], d[2], d[3], ah0, ah1, ah2, ah3, bl[nt][0], bl[nt][1]);
                    mma_bf16(d[0], d[1], d[2], d[3], ah0, ah1, ah2, ah3, bh[nt][0], bh[nt][1]);
                }
            }
        }
        __syncthreads();
    }
    #undef PREFETCH

    #pragma unroll
    for (int mt = 0; mt < 4; mt++) {
        const int row0 = rowBase + warp_m * 64 + mt * 16 + r;
        #pragma unroll
        for (int nt = 0; nt < 4; nt++) {
            const int col = colBase + warp_n * 32 + nt * 8 + 2 * cq;
            float b0v = 0.f, b1v = 0.f;
            if (bias) { b0v = bias[col]; b1v = bias[col + 1]; }
            float2 p0 = make_float2(acc[mt][nt][0] + b0v, acc[mt][nt][1] + b1v);
            float2 p1 = make_float2(acc[mt][nt][2] + b0v, acc[mt][nt][3] + b1v);
            *(float2*)&C[(size_t)row0 * Ncols + col]       = p0;
            *(float2*)&C[(size_t)(row0 + 8) * Ncols + col] = p1;
        }
    }
}

// ============================================================
// sigma: one warp per (b,n); each THREAD accumulates all 8 heads,
// Wsig reads fully coalesced (2x float4 per lane = 1KB/warp).
// ============================================================
__global__ __launch_bounds__(256)
void sigma_kernel(const float* __restrict__ x, const float4* __restrict__ Wsig,
                  const float* __restrict__ bsig, float* __restrict__ inv_out)
{
    const int warp = threadIdx.x >> 5;
    const int lane = threadIdx.x & 31;
    const int bn = blockIdx.x * 8 + warp;
    const int b = bn / N;
    const int n = bn % N;

    const float* xrow = x + (size_t)bn * D;
    float acc[HEADS];
    #pragma unroll
    for (int h = 0; h < HEADS; h++) acc[h] = 0.f;

    #pragma unroll
    for (int it = 0; it < D / 32; it++) {
        const int d = lane + 32 * it;
        const float xv = __ldg(&xrow[d]);
        const float4 w0 = __ldg(&Wsig[d * 2 + 0]);
        const float4 w1 = __ldg(&Wsig[d * 2 + 1]);
        acc[0] += xv * w0.x;  acc[1] += xv * w0.y;
        acc[2] += xv * w0.z;  acc[3] += xv * w0.w;
        acc[4] += xv * w1.x;  acc[5] += xv * w1.y;
        acc[6] += xv * w1.z;  acc[7] += xv * w1.w;
    }

    #pragma unroll
    for (int off = 16; off > 0; off >>= 1)
        #pragma unroll
        for (int h = 0; h < HEADS; h++)
            acc[h] += __shfl_xor_sync(0xFFFFFFFFu, acc[h], off);

    if (lane < HEADS) {
        const int h = lane;
        float s = acc[h] + __ldg(&bsig[h]);
        float sig = 1.f / (1.f + expf(-s));
        float denom = expf(sig) + 1.f;
        inv_out[((size_t)b * HEADS + h) * N + n] = 1.f / denom;
    }
}

// ============================================================
// Band kernel: 8 consecutive rows/thread, geometric running weights,
// exact analytic Z, bf16 hi/lo emit. (proven)
// ============================================================
__global__ __launch_bounds__(512)
void band_kernel(const float* __restrict__ v, const float* __restrict__ inv_arr,
                 unsigned short* __restrict__ ahi, unsigned short* __restrict__ alo)
{
    __shared__ float vs[RB + 2 * BW][DH];   // 48KB

    const int b  = blockIdx.z;
    const int h  = blockIdx.y;
    const int i0 = blockIdx.x * RB;
    const int tid  = threadIdx.x;
    const int lane = tid & 63;
    const int g    = tid >> 6;

    for (int t = tid; t < (RB + 2 * BW) * (DH / 4); t += 512) {
        const int row = t >> 4;
        const int c4  = (t & 15) * 4;
        const int jj  = i0 - BW + row;
        float4 val = make_float4(0.f, 0.f, 0.f, 0.f);
        if (jj >= 0 && jj < N)
            val = __ldg((const float4*)&v[((size_t)(b * N + jj)) * INNER + h * DH + c4]);
        *(float4*)&vs[row][c4] = val;
    }
    __syncthreads();

    const float* invp = inv_arr + ((size_t)b * HEADS + h) * N;
    const int base = i0 + g * 8;

    float rr[8], iv[8], acc[8], w[8];
    #pragma unroll
    for (int t = 0; t < 8; t++) {
        iv[t]  = invp[base + t];
        rr[t]  = __expf(-iv[t]);
        acc[t] = 0.f;
    }

    #pragma unroll
    for (int t = 0; t < 8; t++) w[t] = __expf((float)(7 - t) * iv[t]);
    {
        int jl = g * 8 + 71;
        #pragma unroll
        for (int m = 0; m < 8; m++) {
            const float val = vs[jl][lane];
            #pragma unroll
            for (int t = 0; t < 8; t++) {
                if (m + t >= 7) acc[t] += w[t] * val;
                w[t] *= rr[t];
            }
            jl--;
        }
        #pragma unroll 8
        for (int m = 8; m < 72; m++) {
            const float val = vs[jl][lane];
            #pragma unroll
            for (int t = 0; t < 8; t++) { acc[t] += w[t] * val; w[t] *= rr[t]; }
            jl--;
        }
    }

    #pragma unroll
    for (int t = 0; t < 8; t++) w[t] = __expf((float)t * iv[t]);
    {
        int jl = g * 8 + 64;
        #pragma unroll
        for (int m = 0; m < 8; m++) {
            const float val = vs[jl][lane];
            #pragma unroll
            for (int t = 0; t < 8; t++) {
                if (m >= t + 1) acc[t] += w[t] * val;
                w[t] *= rr[t];
            }
            jl++;
        }
        #pragma unroll 8
        for (int m = 8; m < 72; m++) {
            const float val = vs[jl][lane];
            #pragma unroll
            for (int t = 0; t < 8; t++) { acc[t] += w[t] * val; w[t] *= rr[t]; }
            jl++;
        }
    }

    #pragma unroll
    for (int t = 0; t < 8; t++) {
        const int i = base + t;
        const float r_ = rr[t];
        const float Z = (1.f - __expf(-(float)(i + 1) * iv[t])
                         + r_ - __expf(-(float)(N - i) * iv[t])) / (1.f - r_);
        const float o = acc[t] / Z;
        const uint32_t ob = __float_as_uint(o);
        const size_t idx = ((size_t)(b * N + i)) * INNER + h * DH + lane;
        ahi[idx] = (unsigned short)(ob >> 16);
        const float lof = o - __uint_as_float(ob & 0xFFFF0000u);
        __nv_bfloat16 lb = __float2bfloat16(lof);
        alo[idx] = *reinterpret_cast<unsigned short*>(&lb);
    }
}

// ============================================================
// Launch: x, W_v, W_sigma, b_sigma, W_out, b_out
// ============================================================
extern "C" void kernel_launch(void* const* d_in, const int* in_sizes, int n_in,
                              void* d_out, int out_size)
{
    const float* x     = (const float*)d_in[0];
    const float* W_v   = (const float*)d_in[1];
    const float* W_sig = (const float*)d_in[2];
    const float* b_sig = (const float*)d_in[3];
    const float* W_out = (const float*)d_in[4];
    const float* b_out = (const float*)d_in[5];
    float* out = (float*)d_out;

    uint32_t *xhi, *xlo, *wvt_hi, *wvt_lo, *wot_hi, *wot_lo;
    float *v, *inv;
    unsigned short *ahi, *alo;
    cudaGetSymbolAddress((void**)&xhi, g_xhi);
    cudaGetSymbolAddress((void**)&xlo, g_xlo);
    cudaGetSymbolAddress((void**)&wvt_hi, g_wvt_hi);
    cudaGetSymbolAddress((void**)&wvt_lo, g_wvt_lo);
    cudaGetSymbolAddress((void**)&wot_hi, g_wot_hi);
    cudaGetSymbolAddress((void**)&wot_lo, g_wot_lo);
    cudaGetSymbolAddress((void**)&v, g_v);
    cudaGetSymbolAddress((void**)&inv, g_inv);
    cudaGetSymbolAddress((void**)&ahi, g_ahi);
    cudaGetSymbolAddress((void**)&alo, g_alo);

    static bool attr_set = false;
    if (!attr_set) {
        cudaFuncSetAttribute(gemm_bf16x3_kernel,
                             cudaFuncAttributeMaxDynamicSharedMemorySize,
                             GEMM_SMEM_BYTES);
        attr_set = true;
    }

    // split x into bf16 hi/lo
    {
        const int n4 = M_ROWS * D / 4;
        convert_split_kernel<<<n4 / 256, 256>>>((const float4*)x, (uint2*)xhi, (uint2*)xlo, n4);
    }
    // transpose+split weights
    {
        dim3 grid(INNER / 32, D / 32);
        convert_wt_kernel<<<grid, 256>>>(W_v, wvt_hi, wvt_lo, D, INNER);
    }
    {
        dim3 grid(D / 32, INNER / 32);
        convert_wt_kernel<<<grid, 256>>>(W_out, wot_hi, wot_lo, INNER, D);
    }
    // v = x @ W_v
    {
        dim3 grid(INNER / 128, M_ROWS / 128);
        gemm_bf16x3_kernel<<<grid, 256, GEMM_SMEM_BYTES>>>(xhi, xlo, wvt_hi, wvt_lo,
                                                           nullptr, v, M_ROWS, INNER, D);
    }
    // sigma
    sigma_kernel<<<M_ROWS / 8, 256>>>(x, (const float4*)W_sig, b_sig, inv);
    // banded prior @ v -> attn hi/lo
    {
        dim3 grid(N / RB, HEADS, B);
        band_kernel<<<grid, 512>>>(v, inv, ahi, alo);
    }
    // out = attn @ W_out + b_out
    {
        dim3 grid(D / 128, M_ROWS / 128);
        gemm_bf16x3_kernel<<<grid, 256, GEMM_SMEM_BYTES>>>((const uint32_t*)ahi,
                                                           (const uint32_t*)alo,
                                                           wot_hi, wot_lo, b_out, out,
                                                           M_ROWS, D, INNER);
    }
}

// round 10
// speedup vs baseline: 2.8514x; 1.1362x over previous
#include <cuda_runtime.h>
#include <cuda_bf16.h>
#include <math.h>
#include <stdint.h>

// Problem constants
#define B     4
#define N     2048
#define D     512
#define HEADS 8
#define DH    64
#define INNER 512
#define M_ROWS (B*N)        // 8192
#define KU512  (512/2)      // 256 u32 (bf16 pairs) per row of K=512

// Band params
#define BW 64
#define RB 64

// GEMM smem geometry (u32 units)
#define ROWSTRIDE 20                    // 16 payload + 4 pad (conflict-free, incl. ldmatrix)
#define ARR_U32   (128 * ROWSTRIDE)     // 2560 u32 per array
#define STAGE_U32 (4 * ARR_U32)         // 10240 u32 = 40KB per stage
#define GEMM_SMEM_BYTES (2 * STAGE_U32 * 4)  // 81920

// ---------------- scratch (__device__ globals; no allocation) ----------------
__device__ uint32_t g_xhi[M_ROWS * KU512];
__device__ uint32_t g_xlo[M_ROWS * KU512];
__device__ uint32_t g_wvt_hi[INNER * KU512];
__device__ uint32_t g_wvt_lo[INNER * KU512];
__device__ uint32_t g_wot_hi[D * (INNER/2)];
__device__ uint32_t g_wot_lo[D * (INNER/2)];
__device__ float    g_v[M_ROWS * INNER];
__device__ unsigned short g_ahi[M_ROWS * INNER];
__device__ unsigned short g_alo[M_ROWS * INNER];
__device__ float    g_inv[B*HEADS*N];

// ---------------- helpers ----------------
__device__ __forceinline__ uint32_t pack_bf16rn(float a, float b) {
    __nv_bfloat162 t = __floats2bfloat162_rn(a, b);
    return *reinterpret_cast<uint32_t*>(&t);
}

__device__ __forceinline__ void mma_bf16(float& d0, float& d1, float& d2, float& d3,
                                         uint32_t a0, uint32_t a1, uint32_t a2, uint32_t a3,
                                         uint32_t b0, uint32_t b1) {
    asm volatile(
        "mma.sync.aligned.m16n8k16.row.col.f32.bf16.bf16.f32 "
        "{%0,%1,%2,%3}, {%4,%5,%6,%7}, {%8,%9}, {%0,%1,%2,%3};\n"
        : "+f"(d0), "+f"(d1), "+f"(d2), "+f"(d3)
        : "r"(a0), "r"(a1), "r"(a2), "r"(a3), "r"(b0), "r"(b1));
}

__device__ __forceinline__ void ldsm_x4(uint32_t& r0, uint32_t& r1, uint32_t& r2, uint32_t& r3,
                                        uint32_t addr) {
    asm volatile("ldmatrix.sync.aligned.m8n8.x4.shared.b16 {%0,%1,%2,%3}, [%4];\n"
                 : "=r"(r0), "=r"(r1), "=r"(r2), "=r"(r3) : "r"(addr));
}

__device__ __forceinline__ void cp_async16(uint32_t* smem, const uint32_t* gmem) {
    uint32_t s = (uint32_t)__cvta_generic_to_shared(smem);
    asm volatile("cp.async.cg.shared.global [%0], [%1], 16;\n" :: "r"(s), "l"(gmem));
}
__device__ __forceinline__ void cp_commit() { asm volatile("cp.async.commit_group;\n"); }
__device__ __forceinline__ void cp_wait1()  { asm volatile("cp.async.wait_group 1;\n"); }
__device__ __forceinline__ void cp_wait0()  { asm volatile("cp.async.wait_group 0;\n"); }

// ============================================================
// convert_split: fp32 -> (hi bf16 trunc, lo bf16 rn(a-hi)), packed pairs
// ============================================================
__global__ __launch_bounds__(256)
void convert_split_kernel(const float4* __restrict__ in, uint2* __restrict__ hi,
                          uint2* __restrict__ lo, int n4)
{
    int i = blockIdx.x * blockDim.x + threadIdx.x;
    if (i >= n4) return;
    float4 v = in[i];
    uint32_t u0 = __float_as_uint(v.x), u1 = __float_as_uint(v.y);
    uint32_t u2 = __float_as_uint(v.z), u3 = __float_as_uint(v.w);
    uint2 H;
    H.x = __byte_perm(u0, u1, 0x7632);
    H.y = __byte_perm(u2, u3, 0x7632);
    float l0 = v.x - __uint_as_float(u0 & 0xFFFF0000u);
    float l1 = v.y - __uint_as_float(u1 & 0xFFFF0000u);
    float l2 = v.z - __uint_as_float(u2 & 0xFFFF0000u);
    float l3 = v.w - __uint_as_float(u3 & 0xFFFF0000u);
    uint2 L;
    L.x = pack_bf16rn(l0, l1);
    L.y = pack_bf16rn(l2, l3);
    hi[i] = H;
    lo[i] = L;
}

// ============================================================
// convert_wt: transpose W [K][Nc] fp32 -> Wt hi/lo [Nc][K/2] u32
// ============================================================
__global__ __launch_bounds__(256)
void convert_wt_kernel(const float* __restrict__ W, uint32_t* __restrict__ Whi,
                       uint32_t* __restrict__ Wlo, int K, int Nc)
{
    __shared__ float s[32][33];
    const int k0 = blockIdx.y * 32, n0 = blockIdx.x * 32;
    const int tx = threadIdx.x & 31, ty = threadIdx.x >> 5;
    #pragma unroll
    for (int q = 0; q < 4; q++)
        s[ty + 8*q][tx] = W[(size_t)(k0 + ty + 8*q) * Nc + n0 + tx];
    __syncthreads();
    for (int o = threadIdx.x; o < 512; o += 256) {
        const int n  = o >> 4;
        const int kp = o & 15;
        float v0 = s[2*kp][n], v1 = s[2*kp + 1][n];
        uint32_t w0 = __float_as_uint(v0), w1 = __float_as_uint(v1);
        uint32_t hi = __byte_perm(w0, w1, 0x7632);
        float l0 = v0 - __uint_as_float(w0 & 0xFFFF0000u);
        float l1 = v1 - __uint_as_float(w1 & 0xFFFF0000u);
        uint32_t lo = pack_bf16rn(l0, l1);
        size_t oi = (size_t)(n0 + n) * (K >> 1) + (k0 >> 1) + kp;
        Whi[oi] = hi;
        Wlo[oi] = lo;
    }
}

// ============================================================
// bf16x3 tensor GEMM: 2-stage cp.async pipeline + ldmatrix fragment loads.
// Pass-outer / nt-inner mma order: 4 independent accumulators between
// reuses of the same acc (breaks the 3-long dependency chains).
// ============================================================
__global__ __launch_bounds__(256, 2)
void gemm_bf16x3_kernel(const uint32_t* __restrict__ Ahi, const uint32_t* __restrict__ Alo,
                        const uint32_t* __restrict__ Bhi, const uint32_t* __restrict__ Blo,
                        const float* __restrict__ bias, float* __restrict__ C,
                        int Mrows, int Ncols, int K)
{
    extern __shared__ uint32_t smem[];
    const int KUr = K >> 1;
    const int ntiles = KUr >> 4;

    const int tid = threadIdx.x;
    const int wid = tid >> 5, lane = tid & 31;
    const int warp_m = wid & 1;
    const int warp_n = wid >> 1;
    const int r  = lane >> 2;
    const int cq = lane & 3;
    const int rowBase = blockIdx.y * 128;
    const int colBase = blockIdx.x * 128;

    const int cRow = tid >> 2;          // 0..63
    const int cQ4  = (tid & 3) * 4;     // 0,4,8,12

    const int aOffBase = (warp_m * 64 + (lane & 15)) * ROWSTRIDE + ((lane >> 4) << 2);
    const int bOffBase = (warp_n * 32 + (lane & 7) + ((lane >> 4) << 3)) * ROWSTRIDE
                         + (((lane >> 3) & 1) << 2);

    const uint32_t smem_base_addr = (uint32_t)__cvta_generic_to_shared(smem);

    #define PREFETCH(kt, st) do {                                                     \
        uint32_t* s_ = smem + (st) * STAGE_U32;                                       \
        _Pragma("unroll")                                                             \
        for (int half = 0; half < 2; half++) {                                        \
            const int rr_ = cRow + half * 64;                                         \
            const size_t ao_ = (size_t)(rowBase + rr_) * KUr + (kt) + cQ4;            \
            const size_t bo_ = (size_t)(colBase + rr_) * KUr + (kt) + cQ4;            \
            cp_async16(s_ + 0*ARR_U32 + rr_*ROWSTRIDE + cQ4, Ahi + ao_);              \
            cp_async16(s_ + 1*ARR_U32 + rr_*ROWSTRIDE + cQ4, Alo + ao_);              \
            cp_async16(s_ + 2*ARR_U32 + rr_*ROWSTRIDE + cQ4, Bhi + bo_);              \
            cp_async16(s_ + 3*ARR_U32 + rr_*ROWSTRIDE + cQ4, Blo + bo_);              \
        }                                                                             \
    } while (0)

    float acc[4][4][4];
    #pragma unroll
    for (int a = 0; a < 4; a++)
        #pragma unroll
        for (int b_ = 0; b_ < 4; b_++)
            #pragma unroll
            for (int c = 0; c < 4; c++) acc[a][b_][c] = 0.f;

    PREFETCH(0, 0);
    cp_commit();

    for (int t = 0; t < ntiles; t++) {
        if (t + 1 < ntiles) {
            PREFETCH((t + 1) * 16, (t + 1) & 1);
            cp_commit();
            cp_wait1();
        } else {
            cp_wait0();
        }
        __syncthreads();

        const uint32_t stage = smem_base_addr + ((t & 1) * STAGE_U32) * 4;
        const uint32_t aHiB = stage + (0 * ARR_U32 + aOffBase) * 4;
        const uint32_t aLoB = stage + (1 * ARR_U32 + aOffBase) * 4;
        const uint32_t bHiB = stage + (2 * ARR_U32 + bOffBase) * 4;
        const uint32_t bLoB = stage + (3 * ARR_U32 + bOffBase) * 4;

        #pragma unroll
        for (int ks = 0; ks < 2; ks++) {
            const uint32_t kuB = ks * 8 * 4;
            uint32_t bh[4][2], bl[4][2];
            #pragma unroll
            for (int pair = 0; pair < 2; pair++) {
                const uint32_t po = pair * 16 * ROWSTRIDE * 4;
                ldsm_x4(bh[2*pair][0], bh[2*pair][1], bh[2*pair+1][0], bh[2*pair+1][1],
                        bHiB + po + kuB);
                ldsm_x4(bl[2*pair][0], bl[2*pair][1], bl[2*pair+1][0], bl[2*pair+1][1],
                        bLoB + po + kuB);
            }
            #pragma unroll
            for (int mt = 0; mt < 4; mt++) {
                const uint32_t mo = mt * 16 * ROWSTRIDE * 4;
                uint32_t ah0, ah1, ah2, ah3, al0, al1, al2, al3;
                ldsm_x4(ah0, ah1, ah2, ah3, aHiB + mo + kuB);
                ldsm_x4(al0, al1, al2, al3, aLoB + mo + kuB);
                // pass-outer / nt-inner: same per-acc summation order as before,
                // but consecutive mma target different accumulators.
                #pragma unroll
                for (int nt = 0; nt < 4; nt++) {
                    float* d = acc[mt][nt];
                    mma_bf16(d[0], d[1], d[2], d[3], al0, al1, al2, al3, bh[nt][0], bh[nt][1]);
                }
                #pragma unroll
                for (int nt = 0; nt < 4; nt++) {
                    float* d = acc[mt][nt];
                    mma_bf16(d[0], d[1], d[2], d[3], ah0, ah1, ah2, ah3, bl[nt][0], bl[nt][1]);
                }
                #pragma unroll
                for (int nt = 0; nt < 4; nt++) {
                    float* d = acc[mt][nt];
                    mma_bf16(d[0], d[1], d[2], d[3], ah0, ah1, ah2, ah3, bh[nt][0], bh[nt][1]);
                }
            }
        }
        __syncthreads();
    }
    #undef PREFETCH

    #pragma unroll
    for (int mt = 0; mt < 4; mt++) {
        const int row0 = rowBase + warp_m * 64 + mt * 16 + r;
        #pragma unroll
        for (int nt = 0; nt < 4; nt++) {
            const int col = colBase + warp_n * 32 + nt * 8 + 2 * cq;
            float b0v = 0.f, b1v = 0.f;
            if (bias) { b0v = bias[col]; b1v = bias[col + 1]; }
            float2 p0 = make_float2(acc[mt][nt][0] + b0v, acc[mt][nt][1] + b1v);
            float2 p1 = make_float2(acc[mt][nt][2] + b0v, acc[mt][nt][3] + b1v);
            *(float2*)&C[(size_t)row0 * Ncols + col]       = p0;
            *(float2*)&C[(size_t)(row0 + 8) * Ncols + col] = p1;
        }
    }
}

// ============================================================
// sigma: one warp per (b,n); each THREAD accumulates all 8 heads,
// Wsig reads fully coalesced.
// ============================================================
__global__ __launch_bounds__(256)
void sigma_kernel(const float* __restrict__ x, const float4* __restrict__ Wsig,
                  const float* __restrict__ bsig, float* __restrict__ inv_out)
{
    const int warp = threadIdx.x >> 5;
    const int lane = threadIdx.x & 31;
    const int bn = blockIdx.x * 8 + warp;
    const int b = bn / N;
    const int n = bn % N;

    const float* xrow = x + (size_t)bn * D;
    float acc[HEADS];
    #pragma unroll
    for (int h = 0; h < HEADS; h++) acc[h] = 0.f;

    #pragma unroll
    for (int it = 0; it < D / 32; it++) {
        const int d = lane + 32 * it;
        const float xv = __ldg(&xrow[d]);
        const float4 w0 = __ldg(&Wsig[d * 2 + 0]);
        const float4 w1 = __ldg(&Wsig[d * 2 + 1]);
        acc[0] += xv * w0.x;  acc[1] += xv * w0.y;
        acc[2] += xv * w0.z;  acc[3] += xv * w0.w;
        acc[4] += xv * w1.x;  acc[5] += xv * w1.y;
        acc[6] += xv * w1.z;  acc[7] += xv * w1.w;
    }

    #pragma unroll
    for (int off = 16; off > 0; off >>= 1)
        #pragma unroll
        for (int h = 0; h < HEADS; h++)
            acc[h] += __shfl_xor_sync(0xFFFFFFFFu, acc[h], off);

    if (lane < HEADS) {
        const int h = lane;
        float s = acc[h] + __ldg(&bsig[h]);
        float sig = 1.f / (1.f + expf(-s));
        float denom = expf(sig) + 1.f;
        inv_out[((size_t)b * HEADS + h) * N + n] = 1.f / denom;
    }
}

// ============================================================
// Band kernel — HORNER form: acc = acc*r + v_j (1 FMA/step/row,
// no weight chain). Left sweep ascending j (center included),
// right sweep descending j, combine out = accL + r*accR.
// Far-tail extra terms (distance 65..71, weight <= r^65 ~ 1e-9) are
// true softmax mass — harmless. Exact analytic Z unchanged.
// ============================================================
__global__ __launch_bounds__(512)
void band_kernel(const float* __restrict__ v, const float* __restrict__ inv_arr,
                 unsigned short* __restrict__ ahi, unsigned short* __restrict__ alo)
{
    __shared__ float vs[RB + 2 * BW][DH];   // 192 x 64 = 48KB

    const int b  = blockIdx.z;
    const int h  = blockIdx.y;
    const int i0 = blockIdx.x * RB;
    const int tid  = threadIdx.x;
    const int lane = tid & 63;
    const int g    = tid >> 6;              // 0..7

    for (int t = tid; t < (RB + 2 * BW) * (DH / 4); t += 512) {
        const int row = t >> 4;
        const int c4  = (t & 15) * 4;
        const int jj  = i0 - BW + row;
        float4 val = make_float4(0.f, 0.f, 0.f, 0.f);
        if (jj >= 0 && jj < N)
            val = __ldg((const float4*)&v[((size_t)(b * N + jj)) * INNER + h * DH + c4]);
        *(float4*)&vs[row][c4] = val;
    }
    __syncthreads();

    const float* invp = inv_arr + ((size_t)b * HEADS + h) * N;
    const int base = i0 + g * 8;            // global row of t=0

    float rr[8], iv[8], accL[8], accR[8];
    #pragma unroll
    for (int t = 0; t < 8; t++) {
        iv[t]   = invp[base + t];
        rr[t]   = __expf(-iv[t]);
        accL[t] = 0.f;
        accR[t] = 0.f;
    }

    // ---- Left sweep: j ascending. Row t center at local jl = g*8 + 64 + t. ----
    {
        int jl = g * 8;
        #pragma unroll 8
        for (int m = 0; m < 64; m++) {      // all rows active
            const float val = vs[jl][lane];
            #pragma unroll
            for (int t = 0; t < 8; t++) accL[t] = fmaf(accL[t], rr[t], val);
            jl++;
        }
        #pragma unroll
        for (int m = 64; m < 72; m++) {     // row t active iff t >= m-64
            const float val = vs[jl][lane];
            #pragma unroll
            for (int t = 0; t < 8; t++)
                if (t >= m - 64) accL[t] = fmaf(accL[t], rr[t], val);
            jl++;
        }
    }

    // ---- Right sweep: j descending down to center+1. ----
    {
        int jl = g * 8 + 135;               // row7 center+64
        #pragma unroll 8
        for (int m = 0; m < 64; m++) {      // all rows active (jl >= g*8+72)
            const float val = vs[jl][lane];
            #pragma unroll
            for (int t = 0; t < 8; t++) accR[t] = fmaf(accR[t], rr[t], val);
            jl--;
        }
        #pragma unroll
        for (int m = 64; m < 71; m++) {     // row t active iff t <= 70-m
            const float val = vs[jl][lane];
            #pragma unroll
            for (int t = 0; t < 8; t++)
                if (t <= 70 - m) accR[t] = fmaf(accR[t], rr[t], val);
            jl--;
        }
    }

    // ---- combine, normalize (exact analytic Z), emit bf16 hi/lo ----
    #pragma unroll
    for (int t = 0; t < 8; t++) {
        const int i = base + t;
        const float r_ = rr[t];
        const float sum = fmaf(r_, accR[t], accL[t]);
        const float Z = (1.f - __expf(-(float)(i + 1) * iv[t])
                         + r_ - __expf(-(float)(N - i) * iv[t])) / (1.f - r_);
        const float o = sum / Z;
        const uint32_t ob = __float_as_uint(o);
        const size_t idx = ((size_t)(b * N + i)) * INNER + h * DH + lane;
        ahi[idx] = (unsigned short)(ob >> 16);
        const float lof = o - __uint_as_float(ob & 0xFFFF0000u);
        __nv_bfloat16 lb = __float2bfloat16(lof);
        alo[idx] = *reinterpret_cast<unsigned short*>(&lb);
    }
}

// ============================================================
// Launch: x, W_v, W_sigma, b_sigma, W_out, b_out
// ============================================================
extern "C" void kernel_launch(void* const* d_in, const int* in_sizes, int n_in,
                              void* d_out, int out_size)
{
    const float* x     = (const float*)d_in[0];
    const float* W_v   = (const float*)d_in[1];
    const float* W_sig = (const float*)d_in[2];
    const float* b_sig = (const float*)d_in[3];
    const float* W_out = (const float*)d_in[4];
    const float* b_out = (const float*)d_in[5];
    float* out = (float*)d_out;

    uint32_t *xhi, *xlo, *wvt_hi, *wvt_lo, *wot_hi, *wot_lo;
    float *v, *inv;
    unsigned short *ahi, *alo;
    cudaGetSymbolAddress((void**)&xhi, g_xhi);
    cudaGetSymbolAddress((void**)&xlo, g_xlo);
    cudaGetSymbolAddress((void**)&wvt_hi, g_wvt_hi);
    cudaGetSymbolAddress((void**)&wvt_lo, g_wvt_lo);
    cudaGetSymbolAddress((void**)&wot_hi, g_wot_hi);
    cudaGetSymbolAddress((void**)&wot_lo, g_wot_lo);
    cudaGetSymbolAddress((void**)&v, g_v);
    cudaGetSymbolAddress((void**)&inv, g_inv);
    cudaGetSymbolAddress((void**)&ahi, g_ahi);
    cudaGetSymbolAddress((void**)&alo, g_alo);

    static bool attr_set = false;
    if (!attr_set) {
        cudaFuncSetAttribute(gemm_bf16x3_kernel,
                             cudaFuncAttributeMaxDynamicSharedMemorySize,
                             GEMM_SMEM_BYTES);
        attr_set = true;
    }

    // split x into bf16 hi/lo
    {
        const int n4 = M_ROWS * D / 4;
        convert_split_kernel<<<n4 / 256, 256>>>((const float4*)x, (uint2*)xhi, (uint2*)xlo, n4);
    }
    // transpose+split weights
    {
        dim3 grid(INNER / 32, D / 32);
        convert_wt_kernel<<<grid, 256>>>(W_v, wvt_hi, wvt_lo, D, INNER);
    }
    {
        dim3 grid(D / 32, INNER / 32);
        convert_wt_kernel<<<grid, 256>>>(W_out, wot_hi, wot_lo, INNER, D);
    }
    // v = x @ W_v
    {
        dim3 grid(INNER / 128, M_ROWS / 128);
        gemm_bf16x3_kernel<<<grid, 256, GEMM_SMEM_BYTES>>>(xhi, xlo, wvt_hi, wvt_lo,
                                                           nullptr, v, M_ROWS, INNER, D);
    }
    // sigma
    sigma_kernel<<<M_ROWS / 8, 256>>>(x, (const float4*)W_sig, b_sig, inv);
    // banded prior @ v -> attn hi/lo
    {
        dim3 grid(N / RB, HEADS, B);
        band_kernel<<<grid, 512>>>(v, inv, ahi, alo);
    }
    // out = attn @ W_out + b_out
    {
        dim3 grid(D / 128, M_ROWS / 128);
        gemm_bf16x3_kernel<<<grid, 256, GEMM_SMEM_BYTES>>>((const uint32_t*)ahi,
                                                           (const uint32_t*)alo,
                                                           wot_hi, wot_lo, b_out, out,
                                                           M_ROWS, D, INNER);
    }
}

// round 11
// speedup vs baseline: 3.0150x; 1.0574x over previous
#include <cuda_runtime.h>
#include <cuda_bf16.h>
#include <math.h>
#include <stdint.h>

// Problem constants
#define B     4
#define N     2048
#define D     512
#define HEADS 8
#define DH    64
#define INNER 512
#define M_ROWS (B*N)        // 8192
#define KU512  (512/2)      // 256 u32 (bf16 pairs) per row of K=512

// Band params
#define BW 64
#define RB 64

// GEMM smem geometry (u32 units)
#define ROWSTRIDE 20                    // 16 payload + 4 pad (conflict-free, incl. ldmatrix)
#define ARR_U32   (128 * ROWSTRIDE)     // 2560 u32 per array
#define STAGE_U32 (4 * ARR_U32)         // 10240 u32 = 40KB per stage
#define GEMM_SMEM_BYTES (2 * STAGE_U32 * 4)  // 81920

// ---------------- scratch (__device__ globals; no allocation) ----------------
__device__ uint32_t g_xhi[M_ROWS * KU512];
__device__ uint32_t g_xlo[M_ROWS * KU512];
__device__ uint32_t g_wvt_hi[INNER * KU512];
__device__ uint32_t g_wvt_lo[INNER * KU512];
__device__ uint32_t g_wot_hi[D * (INNER/2)];
__device__ uint32_t g_wot_lo[D * (INNER/2)];
__device__ float    g_v[M_ROWS * INNER];
__device__ unsigned short g_ahi[M_ROWS * INNER];
__device__ unsigned short g_alo[M_ROWS * INNER];
__device__ float    g_inv[B*HEADS*N];

// ---------------- helpers ----------------
__device__ __forceinline__ uint32_t pack_bf16rn(float a, float b) {
    __nv_bfloat162 t = __floats2bfloat162_rn(a, b);
    return *reinterpret_cast<uint32_t*>(&t);
}

__device__ __forceinline__ void mma_bf16(float& d0, float& d1, float& d2, float& d3,
                                         uint32_t a0, uint32_t a1, uint32_t a2, uint32_t a3,
                                         uint32_t b0, uint32_t b1) {
    asm volatile(
        "mma.sync.aligned.m16n8k16.row.col.f32.bf16.bf16.f32 "
        "{%0,%1,%2,%3}, {%4,%5,%6,%7}, {%8,%9}, {%0,%1,%2,%3};\n"
        : "+f"(d0), "+f"(d1), "+f"(d2), "+f"(d3)
        : "r"(a0), "r"(a1), "r"(a2), "r"(a3), "r"(b0), "r"(b1));
}

__device__ __forceinline__ void ldsm_x4(uint32_t& r0, uint32_t& r1, uint32_t& r2, uint32_t& r3,
                                        uint32_t addr) {
    asm volatile("ldmatrix.sync.aligned.m8n8.x4.shared.b16 {%0,%1,%2,%3}, [%4];\n"
                 : "=r"(r0), "=r"(r1), "=r"(r2), "=r"(r3) : "r"(addr));
}

__device__ __forceinline__ void cp_async16(uint32_t* smem, const uint32_t* gmem) {
    uint32_t s = (uint32_t)__cvta_generic_to_shared(smem);
    asm volatile("cp.async.cg.shared.global [%0], [%1], 16;\n" :: "r"(s), "l"(gmem));
}
__device__ __forceinline__ void cp_commit() { asm volatile("cp.async.commit_group;\n"); }
__device__ __forceinline__ void cp_wait1()  { asm volatile("cp.async.wait_group 1;\n"); }
__device__ __forceinline__ void cp_wait0()  { asm volatile("cp.async.wait_group 0;\n"); }

// ---------------- packed f32x2 (Blackwell base ISA, PTX 8.6) ----------------
__device__ __forceinline__ uint64_t f32x2_pack(float lo, float hi) {
    float2 t = make_float2(lo, hi);
    return *reinterpret_cast<uint64_t*>(&t);
}
__device__ __forceinline__ float2 f32x2_unpack(uint64_t v) {
    return *reinterpret_cast<float2*>(&v);
}
__device__ __forceinline__ uint64_t fma2(uint64_t a, uint64_t b, uint64_t c) {
    uint64_t d;
    asm("fma.rn.f32x2 %0, %1, %2, %3;" : "=l"(d) : "l"(a), "l"(b), "l"(c));
    return d;
}
__device__ __forceinline__ uint64_t mul2(uint64_t a, uint64_t b) {
    uint64_t d;
    asm("mul.rn.f32x2 %0, %1, %2;" : "=l"(d) : "l"(a), "l"(b));
    return d;
}

// ============================================================
// convert_split: fp32 -> (hi bf16 trunc, lo bf16 rn(a-hi)), packed pairs
// ============================================================
__global__ __launch_bounds__(256)
void convert_split_kernel(const float4* __restrict__ in, uint2* __restrict__ hi,
                          uint2* __restrict__ lo, int n4)
{
    int i = blockIdx.x * blockDim.x + threadIdx.x;
    if (i >= n4) return;
    float4 v = in[i];
    uint32_t u0 = __float_as_uint(v.x), u1 = __float_as_uint(v.y);
    uint32_t u2 = __float_as_uint(v.z), u3 = __float_as_uint(v.w);
    uint2 H;
    H.x = __byte_perm(u0, u1, 0x7632);
    H.y = __byte_perm(u2, u3, 0x7632);
    float l0 = v.x - __uint_as_float(u0 & 0xFFFF0000u);
    float l1 = v.y - __uint_as_float(u1 & 0xFFFF0000u);
    float l2 = v.z - __uint_as_float(u2 & 0xFFFF0000u);
    float l3 = v.w - __uint_as_float(u3 & 0xFFFF0000u);
    uint2 L;
    L.x = pack_bf16rn(l0, l1);
    L.y = pack_bf16rn(l2, l3);
    hi[i] = H;
    lo[i] = L;
}

// ============================================================
// convert_wt: transpose W [K][Nc] fp32 -> Wt hi/lo [Nc][K/2] u32
// ============================================================
__global__ __launch_bounds__(256)
void convert_wt_kernel(const float* __restrict__ W, uint32_t* __restrict__ Whi,
                       uint32_t* __restrict__ Wlo, int K, int Nc)
{
    __shared__ float s[32][33];
    const int k0 = blockIdx.y * 32, n0 = blockIdx.x * 32;
    const int tx = threadIdx.x & 31, ty = threadIdx.x >> 5;
    #pragma unroll
    for (int q = 0; q < 4; q++)
        s[ty + 8*q][tx] = W[(size_t)(k0 + ty + 8*q) * Nc + n0 + tx];
    __syncthreads();
    for (int o = threadIdx.x; o < 512; o += 256) {
        const int n  = o >> 4;
        const int kp = o & 15;
        float v0 = s[2*kp][n], v1 = s[2*kp + 1][n];
        uint32_t w0 = __float_as_uint(v0), w1 = __float_as_uint(v1);
        uint32_t hi = __byte_perm(w0, w1, 0x7632);
        float l0 = v0 - __uint_as_float(w0 & 0xFFFF0000u);
        float l1 = v1 - __uint_as_float(w1 & 0xFFFF0000u);
        uint32_t lo = pack_bf16rn(l0, l1);
        size_t oi = (size_t)(n0 + n) * (K >> 1) + (k0 >> 1) + kp;
        Whi[oi] = hi;
        Wlo[oi] = lo;
    }
}

// ============================================================
// bf16x3 tensor GEMM: 2-stage cp.async pipeline + ldmatrix fragment loads.
// (proven at 48.5us/GEMM; parked — mma.sync dispatch-ceiling bound)
// ============================================================
__global__ __launch_bounds__(256, 2)
void gemm_bf16x3_kernel(const uint32_t* __restrict__ Ahi, const uint32_t* __restrict__ Alo,
                        const uint32_t* __restrict__ Bhi, const uint32_t* __restrict__ Blo,
                        const float* __restrict__ bias, float* __restrict__ C,
                        int Mrows, int Ncols, int K)
{
    extern __shared__ uint32_t smem[];
    const int KUr = K >> 1;
    const int ntiles = KUr >> 4;

    const int tid = threadIdx.x;
    const int wid = tid >> 5, lane = tid & 31;
    const int warp_m = wid & 1;
    const int warp_n = wid >> 1;
    const int r  = lane >> 2;
    const int cq = lane & 3;
    const int rowBase = blockIdx.y * 128;
    const int colBase = blockIdx.x * 128;

    const int cRow = tid >> 2;          // 0..63
    const int cQ4  = (tid & 3) * 4;     // 0,4,8,12

    const int aOffBase = (warp_m * 64 + (lane & 15)) * ROWSTRIDE + ((lane >> 4) << 2);
    const int bOffBase = (warp_n * 32 + (lane & 7) + ((lane >> 4) << 3)) * ROWSTRIDE
                         + (((lane >> 3) & 1) << 2);

    const uint32_t smem_base_addr = (uint32_t)__cvta_generic_to_shared(smem);

    #define PREFETCH(kt, st) do {                                                     \
        uint32_t* s_ = smem + (st) * STAGE_U32;                                       \
        _Pragma("unroll")                                                             \
        for (int half = 0; half < 2; half++) {                                        \
            const int rr_ = cRow + half * 64;                                         \
            const size_t ao_ = (size_t)(rowBase + rr_) * KUr + (kt) + cQ4;            \
            const size_t bo_ = (size_t)(colBase + rr_) * KUr + (kt) + cQ4;            \
            cp_async16(s_ + 0*ARR_U32 + rr_*ROWSTRIDE + cQ4, Ahi + ao_);              \
            cp_async16(s_ + 1*ARR_U32 + rr_*ROWSTRIDE + cQ4, Alo + ao_);              \
            cp_async16(s_ + 2*ARR_U32 + rr_*ROWSTRIDE + cQ4, Bhi + bo_);              \
            cp_async16(s_ + 3*ARR_U32 + rr_*ROWSTRIDE + cQ4, Blo + bo_);              \
        }                                                                             \
    } while (0)

    float acc[4][4][4];
    #pragma unroll
    for (int a = 0; a < 4; a++)
        #pragma unroll
        for (int b_ = 0; b_ < 4; b_++)
            #pragma unroll
            for (int c = 0; c < 4; c++) acc[a][b_][c] = 0.f;

    PREFETCH(0, 0);
    cp_commit();

    for (int t = 0; t < ntiles; t++) {
        if (t + 1 < ntiles) {
            PREFETCH((t + 1) * 16, (t + 1) & 1);
            cp_commit();
            cp_wait1();
        } else {
            cp_wait0();
        }
        __syncthreads();

        const uint32_t stage = smem_base_addr + ((t & 1) * STAGE_U32) * 4;
        const uint32_t aHiB = stage + (0 * ARR_U32 + aOffBase) * 4;
        const uint32_t aLoB = stage + (1 * ARR_U32 + aOffBase) * 4;
        const uint32_t bHiB = stage + (2 * ARR_U32 + bOffBase) * 4;
        const uint32_t bLoB = stage + (3 * ARR_U32 + bOffBase) * 4;

        #pragma unroll
        for (int ks = 0; ks < 2; ks++) {
            const uint32_t kuB = ks * 8 * 4;
            uint32_t bh[4][2], bl[4][2];
            #pragma unroll
            for (int pair = 0; pair < 2; pair++) {
                const uint32_t po = pair * 16 * ROWSTRIDE * 4;
                ldsm_x4(bh[2*pair][0], bh[2*pair][1], bh[2*pair+1][0], bh[2*pair+1][1],
                        bHiB + po + kuB);
                ldsm_x4(bl[2*pair][0], bl[2*pair][1], bl[2*pair+1][0], bl[2*pair+1][1],
                        bLoB + po + kuB);
            }
            #pragma unroll
            for (int mt = 0; mt < 4; mt++) {
                const uint32_t mo = mt * 16 * ROWSTRIDE * 4;
                uint32_t ah0, ah1, ah2, ah3, al0, al1, al2, al3;
                ldsm_x4(ah0, ah1, ah2, ah3, aHiB + mo + kuB);
                ldsm_x4(al0, al1, al2, al3, aLoB + mo + kuB);
                #pragma unroll
                for (int nt = 0; nt < 4; nt++) {
                    float* d = acc[mt][nt];
                    mma_bf16(d[0], d[1], d[2], d[3], al0, al1, al2, al3, bh[nt][0], bh[nt][1]);
                }
                #pragma unroll
                for (int nt = 0; nt < 4; nt++) {
                    float* d = acc[mt][nt];
                    mma_bf16(d[0], d[1], d[2], d[3], ah0, ah1, ah2, ah3, bl[nt][0], bl[nt][1]);
                }
                #pragma unroll
                for (int nt = 0; nt < 4; nt++) {
                    float* d = acc[mt][nt];
                    mma_bf16(d[0], d[1], d[2], d[3], ah0, ah1, ah2, ah3, bh[nt][0], bh[nt][1]);
                }
            }
        }
        __syncthreads();
    }
    #undef PREFETCH

    #pragma unroll
    for (int mt = 0; mt < 4; mt++) {
        const int row0 = rowBase + warp_m * 64 + mt * 16 + r;
        #pragma unroll
        for (int nt = 0; nt < 4; nt++) {
            const int col = colBase + warp_n * 32 + nt * 8 + 2 * cq;
            float b0v = 0.f, b1v = 0.f;
            if (bias) { b0v = bias[col]; b1v = bias[col + 1]; }
            float2 p0 = make_float2(acc[mt][nt][0] + b0v, acc[mt][nt][1] + b1v);
            float2 p1 = make_float2(acc[mt][nt][2] + b0v, acc[mt][nt][3] + b1v);
            *(float2*)&C[(size_t)row0 * Ncols + col]       = p0;
            *(float2*)&C[(size_t)(row0 + 8) * Ncols + col] = p1;
        }
    }
}

// ============================================================
// sigma: one warp per (b,n); each THREAD accumulates all 8 heads,
// Wsig reads fully coalesced.
// ============================================================
__global__ __launch_bounds__(256)
void sigma_kernel(const float* __restrict__ x, const float4* __restrict__ Wsig,
                  const float* __restrict__ bsig, float* __restrict__ inv_out)
{
    const int warp = threadIdx.x >> 5;
    const int lane = threadIdx.x & 31;
    const int bn = blockIdx.x * 8 + warp;
    const int b = bn / N;
    const int n = bn % N;

    const float* xrow = x + (size_t)bn * D;
    float acc[HEADS];
    #pragma unroll
    for (int h = 0; h < HEADS; h++) acc[h] = 0.f;

    #pragma unroll
    for (int it = 0; it < D / 32; it++) {
        const int d = lane + 32 * it;
        const float xv = __ldg(&xrow[d]);
        const float4 w0 = __ldg(&Wsig[d * 2 + 0]);
        const float4 w1 = __ldg(&Wsig[d * 2 + 1]);
        acc[0] += xv * w0.x;  acc[1] += xv * w0.y;
        acc[2] += xv * w0.z;  acc[3] += xv * w0.w;
        acc[4] += xv * w1.x;  acc[5] += xv * w1.y;
        acc[6] += xv * w1.z;  acc[7] += xv * w1.w;
    }

    #pragma unroll
    for (int off = 16; off > 0; off >>= 1)
        #pragma unroll
        for (int h = 0; h < HEADS; h++)
            acc[h] += __shfl_xor_sync(0xFFFFFFFFu, acc[h], off);

    if (lane < HEADS) {
        const int h = lane;
        float s = acc[h] + __ldg(&bsig[h]);
        float sig = 1.f / (1.f + expf(-s));
        float denom = expf(sig) + 1.f;
        inv_out[((size_t)b * HEADS + h) * N + n] = 1.f / denom;
    }
}

// ============================================================
// Band kernel — packed f32x2 Horner. Each thread owns a dh PAIR
// (float2 LDS.64) and 4 rows; per step 1 LDS.64 + 4 fma.rn.f32x2
// (halves FFMA issue slots vs scalar). Entry side includes a few
// extra far terms (distance<=67, weight<=1e-9, true softmax mass);
// exit peels stop each row exactly at its center. Exact analytic Z.
// 512 threads: g = tid>>5 (16 groups x 4 rows), lp = tid&31 (dh pair).
// ============================================================
__global__ __launch_bounds__(512)
void band_kernel(const float* __restrict__ v, const float* __restrict__ inv_arr,
                 unsigned short* __restrict__ ahi, unsigned short* __restrict__ alo)
{
    __shared__ float vs[RB + 2 * BW][DH];   // 192 x 64 = 48KB

    const int b  = blockIdx.z;
    const int h  = blockIdx.y;
    const int i0 = blockIdx.x * RB;
    const int tid = threadIdx.x;
    const int lp  = tid & 31;               // dh pair index (dh = 2*lp, 2*lp+1)
    const int g   = tid >> 5;               // 0..15, rows base g*4

    for (int t = tid; t < (RB + 2 * BW) * (DH / 4); t += 512) {
        const int row = t >> 4;
        const int c4  = (t & 15) * 4;
        const int jj  = i0 - BW + row;
        float4 val = make_float4(0.f, 0.f, 0.f, 0.f);
        if (jj >= 0 && jj < N)
            val = __ldg((const float4*)&v[((size_t)(b * N + jj)) * INNER + h * DH + c4]);
        *(float4*)&vs[row][c4] = val;
    }
    __syncthreads();

    const float* invp = inv_arr + ((size_t)b * HEADS + h) * N;
    const int base = i0 + g * 4;            // global row of t=0
    // local center of row t is (g*4 + t) + 64

    float rr[4], iv[4];
    uint64_t rr2[4], accL[4], accR[4];
    #pragma unroll
    for (int t = 0; t < 4; t++) {
        iv[t]   = invp[base + t];
        rr[t]   = __expf(-iv[t]);
        rr2[t]  = f32x2_pack(rr[t], rr[t]);
        accL[t] = 0ull;
        accR[t] = 0ull;
    }

    // ---- Left sweep: j ascending, Horner acc = acc*r + v_j; center included.
    // Row t window [center-64, center]; start at jl=g*4 adds <=3 extra far terms.
    {
        int jl = g * 4;
        #pragma unroll 8
        for (int m = 0; m < 65; m++) {      // all rows active (m <= t+64 for all t)
            const uint64_t v2 = *(const uint64_t*)&vs[jl][2 * lp];
            #pragma unroll
            for (int t = 0; t < 4; t++) accL[t] = fma2(accL[t], rr2[t], v2);
            jl++;
        }
        #pragma unroll
        for (int m = 65; m < 68; m++) {     // row t active iff t >= m-64
            const uint64_t v2 = *(const uint64_t*)&vs[jl][2 * lp];
            #pragma unroll
            for (int t = 0; t < 4; t++)
                if (t >= m - 64) accL[t] = fma2(accL[t], rr2[t], v2);
            jl++;
        }
    }

    // ---- Right sweep: j descending, row t window [center+1, center+64];
    // start at jl=g*4+131 adds <=3 extra far terms for t<3.
    {
        int jl = g * 4 + 131;
        #pragma unroll 8
        for (int m = 0; m < 64; m++) {      // all rows active (131-m >= t+65 for all t)
            const uint64_t v2 = *(const uint64_t*)&vs[jl][2 * lp];
            #pragma unroll
            for (int t = 0; t < 4; t++) accR[t] = fma2(accR[t], rr2[t], v2);
            jl--;
        }
        #pragma unroll
        for (int m = 64; m < 67; m++) {     // row t active iff t <= 66-m
            const uint64_t v2 = *(const uint64_t*)&vs[jl][2 * lp];
            #pragma unroll
            for (int t = 0; t < 4; t++)
                if (t <= 66 - m) accR[t] = fma2(accR[t], rr2[t], v2);
            jl--;
        }
    }

    // ---- combine, normalize (exact analytic Z), emit bf16 hi/lo pairs ----
    #pragma unroll
    for (int t = 0; t < 4; t++) {
        const int i = base + t;
        const float r_ = rr[t];
        const uint64_t sum2 = fma2(rr2[t], accR[t], accL[t]);   // accL + r*accR
        const float Z = (1.f - __expf(-(float)(i + 1) * iv[t])
                         + r_ - __expf(-(float)(N - i) * iv[t])) / (1.f - r_);
        const float zi = 1.f / Z;
        const float2 o = f32x2_unpack(mul2(sum2, f32x2_pack(zi, zi)));

        const size_t idx = ((size_t)(b * N + i)) * INNER + h * DH + 2 * lp;
        const uint32_t ob0 = __float_as_uint(o.x);
        const uint32_t ob1 = __float_as_uint(o.y);
        // hi = truncated top16
        ushort2 hp;
        hp.x = (unsigned short)(ob0 >> 16);
        hp.y = (unsigned short)(ob1 >> 16);
        *(ushort2*)&ahi[idx] = hp;
        // lo = rn(o - hi)
        const float lof0 = o.x - __uint_as_float(ob0 & 0xFFFF0000u);
        const float lof1 = o.y - __uint_as_float(ob1 & 0xFFFF0000u);
        *(uint32_t*)&alo[idx] = pack_bf16rn(lof0, lof1);
    }
}

// ============================================================
// Launch: x, W_v, W_sigma, b_sigma, W_out, b_out
// ============================================================
extern "C" void kernel_launch(void* const* d_in, const int* in_sizes, int n_in,
                              void* d_out, int out_size)
{
    const float* x     = (const float*)d_in[0];
    const float* W_v   = (const float*)d_in[1];
    const float* W_sig = (const float*)d_in[2];
    const float* b_sig = (const float*)d_in[3];
    const float* W_out = (const float*)d_in[4];
    const float* b_out = (const float*)d_in[5];
    float* out = (float*)d_out;

    uint32_t *xhi, *xlo, *wvt_hi, *wvt_lo, *wot_hi, *wot_lo;
    float *v, *inv;
    unsigned short *ahi, *alo;
    cudaGetSymbolAddress((void**)&xhi, g_xhi);
    cudaGetSymbolAddress((void**)&xlo, g_xlo);
    cudaGetSymbolAddress((void**)&wvt_hi, g_wvt_hi);
    cudaGetSymbolAddress((void**)&wvt_lo, g_wvt_lo);
    cudaGetSymbolAddress((void**)&wot_hi, g_wot_hi);
    cudaGetSymbolAddress((void**)&wot_lo, g_wot_lo);
    cudaGetSymbolAddress((void**)&v, g_v);
    cudaGetSymbolAddress((void**)&inv, g_inv);
    cudaGetSymbolAddress((void**)&ahi, g_ahi);
    cudaGetSymbolAddress((void**)&alo, g_alo);

    static bool attr_set = false;
    if (!attr_set) {
        cudaFuncSetAttribute(gemm_bf16x3_kernel,
                             cudaFuncAttributeMaxDynamicSharedMemorySize,
                             GEMM_SMEM_BYTES);
        attr_set = true;
    }

    // split x into bf16 hi/lo
    {
        const int n4 = M_ROWS * D / 4;
        convert_split_kernel<<<n4 / 256, 256>>>((const float4*)x, (uint2*)xhi, (uint2*)xlo, n4);
    }
    // transpose+split weights
    {
        dim3 grid(INNER / 32, D / 32);
        convert_wt_kernel<<<grid, 256>>>(W_v, wvt_hi, wvt_lo, D, INNER);
    }
    {
        dim3 grid(D / 32, INNER / 32);
        convert_wt_kernel<<<grid, 256>>>(W_out, wot_hi, wot_lo, INNER, D);
    }
    // v = x @ W_v
    {
        dim3 grid(INNER / 128, M_ROWS / 128);
        gemm_bf16x3_kernel<<<grid, 256, GEMM_SMEM_BYTES>>>(xhi, xlo, wvt_hi, wvt_lo,
                                                           nullptr, v, M_ROWS, INNER, D);
    }
    // sigma
    sigma_kernel<<<M_ROWS / 8, 256>>>(x, (const float4*)W_sig, b_sig, inv);
    // banded prior @ v -> attn hi/lo
    {
        dim3 grid(N / RB, HEADS, B);
        band_kernel<<<grid, 512>>>(v, inv, ahi, alo);
    }
    // out = attn @ W_out + b_out
    {
        dim3 grid(D / 128, M_ROWS / 128);
        gemm_bf16x3_kernel<<<grid, 256, GEMM_SMEM_BYTES>>>((const uint32_t*)ahi,
                                                           (const uint32_t*)alo,
                                                           wot_hi, wot_lo, b_out, out,
                                                           M_ROWS, D, INNER);
    }
}

// round 12
// speedup vs baseline: 3.2969x; 1.0935x over previous
#include <cuda_runtime.h>
#include <cuda_bf16.h>
#include <cuda_fp16.h>
#include <math.h>
#include <stdint.h>

// Problem constants
#define B     4
#define N     2048
#define D     512
#define HEADS 8
#define DH    64
#define INNER 512
#define M_ROWS (B*N)        // 8192
#define KU512  (512/2)      // 256 u32 (16-bit pairs) per row of K=512

// Band params
#define BW 64
#define RB 64

// bf16x3 GEMM smem geometry (u32 units)
#define ROWSTRIDE 20                    // 16 payload + 4 pad
#define ARR_U32   (128 * ROWSTRIDE)     // 2560 u32 per array
#define STAGE_U32 (4 * ARR_U32)         // 4 arrays = 40KB per stage
#define GEMM_SMEM_BYTES (2 * STAGE_U32 * 4)  // 81920

// fp16 2-pass GEMM smem geometry (3 arrays: A, Bhi, Blo)
#define STAGE3_U32 (3 * ARR_U32)        // 7680 u32 = 30KB per stage
#define GEMM3_SMEM_BYTES (2 * STAGE3_U32 * 4) // 61440

// ---------------- scratch (__device__ globals; no allocation) ----------------
__device__ uint32_t g_xhi[M_ROWS * KU512];
__device__ uint32_t g_xlo[M_ROWS * KU512];
__device__ uint32_t g_wvt_hi[INNER * KU512];
__device__ uint32_t g_wvt_lo[INNER * KU512];
__device__ uint32_t g_wot_hi[D * (INNER/2)];   // W_out^T fp16 hi pairs
__device__ uint32_t g_wot_lo[D * (INNER/2)];   // W_out^T fp16 lo pairs
__device__ float    g_v[M_ROWS * INNER];
__device__ unsigned short g_a16[M_ROWS * INNER];  // attn fp16 (single precision level)
__device__ float    g_inv[B*HEADS*N];

// ---------------- helpers ----------------
__device__ __forceinline__ uint32_t pack_bf16rn(float a, float b) {
    __nv_bfloat162 t = __floats2bfloat162_rn(a, b);
    return *reinterpret_cast<uint32_t*>(&t);
}

__device__ __forceinline__ void mma_bf16(float& d0, float& d1, float& d2, float& d3,
                                         uint32_t a0, uint32_t a1, uint32_t a2, uint32_t a3,
                                         uint32_t b0, uint32_t b1) {
    asm volatile(
        "mma.sync.aligned.m16n8k16.row.col.f32.bf16.bf16.f32 "
        "{%0,%1,%2,%3}, {%4,%5,%6,%7}, {%8,%9}, {%0,%1,%2,%3};\n"
        : "+f"(d0), "+f"(d1), "+f"(d2), "+f"(d3)
        : "r"(a0), "r"(a1), "r"(a2), "r"(a3), "r"(b0), "r"(b1));
}

__device__ __forceinline__ void mma_fp16(float& d0, float& d1, float& d2, float& d3,
                                         uint32_t a0, uint32_t a1, uint32_t a2, uint32_t a3,
                                         uint32_t b0, uint32_t b1) {
    asm volatile(
        "mma.sync.aligned.m16n8k16.row.col.f32.f16.f16.f32 "
        "{%0,%1,%2,%3}, {%4,%5,%6,%7}, {%8,%9}, {%0,%1,%2,%3};\n"
        : "+f"(d0), "+f"(d1), "+f"(d2), "+f"(d3)
        : "r"(a0), "r"(a1), "r"(a2), "r"(a3), "r"(b0), "r"(b1));
}

__device__ __forceinline__ void ldsm_x4(uint32_t& r0, uint32_t& r1, uint32_t& r2, uint32_t& r3,
                                        uint32_t addr) {
    asm volatile("ldmatrix.sync.aligned.m8n8.x4.shared.b16 {%0,%1,%2,%3}, [%4];\n"
                 : "=r"(r0), "=r"(r1), "=r"(r2), "=r"(r3) : "r"(addr));
}

__device__ __forceinline__ void cp_async16(uint32_t* smem, const uint32_t* gmem) {
    uint32_t s = (uint32_t)__cvta_generic_to_shared(smem);
    asm volatile("cp.async.cg.shared.global [%0], [%1], 16;\n" :: "r"(s), "l"(gmem));
}
__device__ __forceinline__ void cp_commit() { asm volatile("cp.async.commit_group;\n"); }
__device__ __forceinline__ void cp_wait1()  { asm volatile("cp.async.wait_group 1;\n"); }
__device__ __forceinline__ void cp_wait0()  { asm volatile("cp.async.wait_group 0;\n"); }

// ---------------- packed f32x2 (Blackwell base ISA) ----------------
__device__ __forceinline__ uint64_t f32x2_pack(float lo, float hi) {
    float2 t = make_float2(lo, hi);
    return *reinterpret_cast<uint64_t*>(&t);
}
__device__ __forceinline__ float2 f32x2_unpack(uint64_t v) {
    return *reinterpret_cast<float2*>(&v);
}
__device__ __forceinline__ uint64_t fma2(uint64_t a, uint64_t b, uint64_t c) {
    uint64_t d;
    asm("fma.rn.f32x2 %0, %1, %2, %3;" : "=l"(d) : "l"(a), "l"(b), "l"(c));
    return d;
}
__device__ __forceinline__ uint64_t mul2(uint64_t a, uint64_t b) {
    uint64_t d;
    asm("mul.rn.f32x2 %0, %1, %2;" : "=l"(d) : "l"(a), "l"(b));
    return d;
}

// ============================================================
// convert_split: fp32 -> (hi bf16 trunc, lo bf16 rn(a-hi)), packed pairs
// ============================================================
__global__ __launch_bounds__(256)
void convert_split_kernel(const float4* __restrict__ in, uint2* __restrict__ hi,
                          uint2* __restrict__ lo, int n4)
{
    int i = blockIdx.x * blockDim.x + threadIdx.x;
    if (i >= n4) return;
    float4 v = in[i];
    uint32_t u0 = __float_as_uint(v.x), u1 = __float_as_uint(v.y);
    uint32_t u2 = __float_as_uint(v.z), u3 = __float_as_uint(v.w);
    uint2 H;
    H.x = __byte_perm(u0, u1, 0x7632);
    H.y = __byte_perm(u2, u3, 0x7632);
    float l0 = v.x - __uint_as_float(u0 & 0xFFFF0000u);
    float l1 = v.y - __uint_as_float(u1 & 0xFFFF0000u);
    float l2 = v.z - __uint_as_float(u2 & 0xFFFF0000u);
    float l3 = v.w - __uint_as_float(u3 & 0xFFFF0000u);
    uint2 L;
    L.x = pack_bf16rn(l0, l1);
    L.y = pack_bf16rn(l2, l3);
    hi[i] = H;
    lo[i] = L;
}

// ============================================================
// convert_wt (bf16): transpose W [K][Nc] fp32 -> Wt hi/lo [Nc][K/2] u32
// ============================================================
__global__ __launch_bounds__(256)
void convert_wt_kernel(const float* __restrict__ W, uint32_t* __restrict__ Whi,
                       uint32_t* __restrict__ Wlo, int K, int Nc)
{
    __shared__ float s[32][33];
    const int k0 = blockIdx.y * 32, n0 = blockIdx.x * 32;
    const int tx = threadIdx.x & 31, ty = threadIdx.x >> 5;
    #pragma unroll
    for (int q = 0; q < 4; q++)
        s[ty + 8*q][tx] = W[(size_t)(k0 + ty + 8*q) * Nc + n0 + tx];
    __syncthreads();
    for (int o = threadIdx.x; o < 512; o += 256) {
        const int n  = o >> 4;
        const int kp = o & 15;
        float v0 = s[2*kp][n], v1 = s[2*kp + 1][n];
        uint32_t w0 = __float_as_uint(v0), w1 = __float_as_uint(v1);
        uint32_t hi = __byte_perm(w0, w1, 0x7632);
        float l0 = v0 - __uint_as_float(w0 & 0xFFFF0000u);
        float l1 = v1 - __uint_as_float(w1 & 0xFFFF0000u);
        uint32_t lo = pack_bf16rn(l0, l1);
        size_t oi = (size_t)(n0 + n) * (K >> 1) + (k0 >> 1) + kp;
        Whi[oi] = hi;
        Wlo[oi] = lo;
    }
}

// ============================================================
// convert_wt_fp16: transpose W [K][Nc] fp32 -> fp16 hi/lo pairs [Nc][K/2]
// hi = rn_fp16(w), lo = rn_fp16(w - hi)
// ============================================================
__global__ __launch_bounds__(256)
void convert_wt_fp16_kernel(const float* __restrict__ W, uint32_t* __restrict__ Whi,
                            uint32_t* __restrict__ Wlo, int K, int Nc)
{
    __shared__ float s[32][33];
    const int k0 = blockIdx.y * 32, n0 = blockIdx.x * 32;
    const int tx = threadIdx.x & 31, ty = threadIdx.x >> 5;
    #pragma unroll
    for (int q = 0; q < 4; q++)
        s[ty + 8*q][tx] = W[(size_t)(k0 + ty + 8*q) * Nc + n0 + tx];
    __syncthreads();
    for (int o = threadIdx.x; o < 512; o += 256) {
        const int n  = o >> 4;
        const int kp = o & 15;
        float v0 = s[2*kp][n], v1 = s[2*kp + 1][n];
        __half h0 = __float2half_rn(v0), h1 = __float2half_rn(v1);
        __half l0 = __float2half_rn(v0 - __half2float(h0));
        __half l1 = __float2half_rn(v1 - __half2float(h1));
        __half2 hp = __halves2half2(h0, h1);   // h0 in low half
        __half2 lp = __halves2half2(l0, l1);
        size_t oi = (size_t)(n0 + n) * (K >> 1) + (k0 >> 1) + kp;
        Whi[oi] = *reinterpret_cast<uint32_t*>(&hp);
        Wlo[oi] = *reinterpret_cast<uint32_t*>(&lp);
    }
}

// ============================================================
// bf16x3 tensor GEMM (GEMM1, proven): 2-stage cp.async + ldmatrix.
// ============================================================
__global__ __launch_bounds__(256, 2)
void gemm_bf16x3_kernel(const uint32_t* __restrict__ Ahi, const uint32_t* __restrict__ Alo,
                        const uint32_t* __restrict__ Bhi, const uint32_t* __restrict__ Blo,
                        const float* __restrict__ bias, float* __restrict__ C,
                        int Mrows, int Ncols, int K)
{
    extern __shared__ uint32_t smem[];
    const int KUr = K >> 1;
    const int ntiles = KUr >> 4;

    const int tid = threadIdx.x;
    const int wid = tid >> 5, lane = tid & 31;
    const int warp_m = wid & 1;
    const int warp_n = wid >> 1;
    const int r  = lane >> 2;
    const int cq = lane & 3;
    const int rowBase = blockIdx.y * 128;
    const int colBase = blockIdx.x * 128;

    const int cRow = tid >> 2;
    const int cQ4  = (tid & 3) * 4;

    const int aOffBase = (warp_m * 64 + (lane & 15)) * ROWSTRIDE + ((lane >> 4) << 2);
    const int bOffBase = (warp_n * 32 + (lane & 7) + ((lane >> 4) << 3)) * ROWSTRIDE
                         + (((lane >> 3) & 1) << 2);

    const uint32_t smem_base_addr = (uint32_t)__cvta_generic_to_shared(smem);

    #define PREFETCH4(kt, st) do {                                                    \
        uint32_t* s_ = smem + (st) * STAGE_U32;                                       \
        _Pragma("unroll")                                                             \
        for (int half = 0; half < 2; half++) {                                        \
            const int rr_ = cRow + half * 64;                                         \
            const size_t ao_ = (size_t)(rowBase + rr_) * KUr + (kt) + cQ4;            \
            const size_t bo_ = (size_t)(colBase + rr_) * KUr + (kt) + cQ4;            \
            cp_async16(s_ + 0*ARR_U32 + rr_*ROWSTRIDE + cQ4, Ahi + ao_);              \
            cp_async16(s_ + 1*ARR_U32 + rr_*ROWSTRIDE + cQ4, Alo + ao_);              \
            cp_async16(s_ + 2*ARR_U32 + rr_*ROWSTRIDE + cQ4, Bhi + bo_);              \
            cp_async16(s_ + 3*ARR_U32 + rr_*ROWSTRIDE + cQ4, Blo + bo_);              \
        }                                                                             \
    } while (0)

    float acc[4][4][4];
    #pragma unroll
    for (int a = 0; a < 4; a++)
        #pragma unroll
        for (int b_ = 0; b_ < 4; b_++)
            #pragma unroll
            for (int c = 0; c < 4; c++) acc[a][b_][c] = 0.f;

    PREFETCH4(0, 0);
    cp_commit();

    for (int t = 0; t < ntiles; t++) {
        if (t + 1 < ntiles) {
            PREFETCH4((t + 1) * 16, (t + 1) & 1);
            cp_commit();
            cp_wait1();
        } else {
            cp_wait0();
        }
        __syncthreads();

        const uint32_t stage = smem_base_addr + ((t & 1) * STAGE_U32) * 4;
        const uint32_t aHiB = stage + (0 * ARR_U32 + aOffBase) * 4;
        const uint32_t aLoB = stage + (1 * ARR_U32 + aOffBase) * 4;
        const uint32_t bHiB = stage + (2 * ARR_U32 + bOffBase) * 4;
        const uint32_t bLoB = stage + (3 * ARR_U32 + bOffBase) * 4;

        #pragma unroll
        for (int ks = 0; ks < 2; ks++) {
            const uint32_t kuB = ks * 8 * 4;
            uint32_t bh[4][2], bl[4][2];
            #pragma unroll
            for (int pair = 0; pair < 2; pair++) {
                const uint32_t po = pair * 16 * ROWSTRIDE * 4;
                ldsm_x4(bh[2*pair][0], bh[2*pair][1], bh[2*pair+1][0], bh[2*pair+1][1],
                        bHiB + po + kuB);
                ldsm_x4(bl[2*pair][0], bl[2*pair][1], bl[2*pair+1][0], bl[2*pair+1][1],
                        bLoB + po + kuB);
            }
            #pragma unroll
            for (int mt = 0; mt < 4; mt++) {
                const uint32_t mo = mt * 16 * ROWSTRIDE * 4;
                uint32_t ah0, ah1, ah2, ah3, al0, al1, al2, al3;
                ldsm_x4(ah0, ah1, ah2, ah3, aHiB + mo + kuB);
                ldsm_x4(al0, al1, al2, al3, aLoB + mo + kuB);
                #pragma unroll
                for (int nt = 0; nt < 4; nt++) {
                    float* d = acc[mt][nt];
                    mma_bf16(d[0], d[1], d[2], d[3], al0, al1, al2, al3, bh[nt][0], bh[nt][1]);
                }
                #pragma unroll
                for (int nt = 0; nt < 4; nt++) {
                    float* d = acc[mt][nt];
                    mma_bf16(d[0], d[1], d[2], d[3], ah0, ah1, ah2, ah3, bl[nt][0], bl[nt][1]);
                }
                #pragma unroll
                for (int nt = 0; nt < 4; nt++) {
                    float* d = acc[mt][nt];
                    mma_bf16(d[0], d[1], d[2], d[3], ah0, ah1, ah2, ah3, bh[nt][0], bh[nt][1]);
                }
            }
        }
        __syncthreads();
    }
    #undef PREFETCH4

    #pragma unroll
    for (int mt = 0; mt < 4; mt++) {
        const int row0 = rowBase + warp_m * 64 + mt * 16 + r;
        #pragma unroll
        for (int nt = 0; nt < 4; nt++) {
            const int col = colBase + warp_n * 32 + nt * 8 + 2 * cq;
            float b0v = 0.f, b1v = 0.f;
            if (bias) { b0v = bias[col]; b1v = bias[col + 1]; }
            float2 p0 = make_float2(acc[mt][nt][0] + b0v, acc[mt][nt][1] + b1v);
            float2 p1 = make_float2(acc[mt][nt][2] + b0v, acc[mt][nt][3] + b1v);
            *(float2*)&C[(size_t)row0 * Ncols + col]       = p0;
            *(float2*)&C[(size_t)(row0 + 8) * Ncols + col] = p1;
        }
    }
}

// ============================================================
// fp16 2-pass GEMM (GEMM2): C = A(fp16) @ [Bhi + Blo]^T + bias.
// A single fp16 (attn rounded), B split into fp16 hi/lo.
// 3 smem arrays per stage (A, Bhi, Blo). 2 mma passes per fragment.
// ============================================================
__global__ __launch_bounds__(256, 2)
void gemm_a16_kernel(const uint32_t* __restrict__ A16, const uint32_t* __restrict__ Bhi,
                     const uint32_t* __restrict__ Blo, const float* __restrict__ bias,
                     float* __restrict__ C, int Ncols, int K)
{
    extern __shared__ uint32_t smem[];
    const int KUr = K >> 1;
    const int ntiles = KUr >> 4;

    const int tid = threadIdx.x;
    const int wid = tid >> 5, lane = tid & 31;
    const int warp_m = wid & 1;
    const int warp_n = wid >> 1;
    const int r  = lane >> 2;
    const int cq = lane & 3;
    const int rowBase = blockIdx.y * 128;
    const int colBase = blockIdx.x * 128;

    const int cRow = tid >> 2;
    const int cQ4  = (tid & 3) * 4;

    const int aOffBase = (warp_m * 64 + (lane & 15)) * ROWSTRIDE + ((lane >> 4) << 2);
    const int bOffBase = (warp_n * 32 + (lane & 7) + ((lane >> 4) << 3)) * ROWSTRIDE
                         + (((lane >> 3) & 1) << 2);

    const uint32_t smem_base_addr = (uint32_t)__cvta_generic_to_shared(smem);

    #define PREFETCH3(kt, st) do {                                                    \
        uint32_t* s_ = smem + (st) * STAGE3_U32;                                      \
        _Pragma("unroll")                                                             \
        for (int half = 0; half < 2; half++) {                                        \
            const int rr_ = cRow + half * 64;                                         \
            const size_t ao_ = (size_t)(rowBase + rr_) * KUr + (kt) + cQ4;            \
            const size_t bo_ = (size_t)(colBase + rr_) * KUr + (kt) + cQ4;            \
            cp_async16(s_ + 0*ARR_U32 + rr_*ROWSTRIDE + cQ4, A16 + ao_);              \
            cp_async16(s_ + 1*ARR_U32 + rr_*ROWSTRIDE + cQ4, Bhi + bo_);              \
            cp_async16(s_ + 2*ARR_U32 + rr_*ROWSTRIDE + cQ4, Blo + bo_);              \
        }                                                                             \
    } while (0)

    float acc[4][4][4];
    #pragma unroll
    for (int a = 0; a < 4; a++)
        #pragma unroll
        for (int b_ = 0; b_ < 4; b_++)
            #pragma unroll
            for (int c = 0; c < 4; c++) acc[a][b_][c] = 0.f;

    PREFETCH3(0, 0);
    cp_commit();

    for (int t = 0; t < ntiles; t++) {
        if (t + 1 < ntiles) {
            PREFETCH3((t + 1) * 16, (t + 1) & 1);
            cp_commit();
            cp_wait1();
        } else {
            cp_wait0();
        }
        __syncthreads();

        const uint32_t stage = smem_base_addr + ((t & 1) * STAGE3_U32) * 4;
        const uint32_t aB   = stage + (0 * ARR_U32 + aOffBase) * 4;
        const uint32_t bHiB = stage + (1 * ARR_U32 + bOffBase) * 4;
        const uint32_t bLoB = stage + (2 * ARR_U32 + bOffBase) * 4;

        #pragma unroll
        for (int ks = 0; ks < 2; ks++) {
            const uint32_t kuB = ks * 8 * 4;
            uint32_t bh[4][2], bl[4][2];
            #pragma unroll
            for (int pair = 0; pair < 2; pair++) {
                const uint32_t po = pair * 16 * ROWSTRIDE * 4;
                ldsm_x4(bh[2*pair][0], bh[2*pair][1], bh[2*pair+1][0], bh[2*pair+1][1],
                        bHiB + po + kuB);
                ldsm_x4(bl[2*pair][0], bl[2*pair][1], bl[2*pair+1][0], bl[2*pair+1][1],
                        bLoB + po + kuB);
            }
            #pragma unroll
            for (int mt = 0; mt < 4; mt++) {
                const uint32_t mo = mt * 16 * ROWSTRIDE * 4;
                uint32_t a0, a1, a2, a3;
                ldsm_x4(a0, a1, a2, a3, aB + mo + kuB);
                #pragma unroll
                for (int nt = 0; nt < 4; nt++) {
                    float* d = acc[mt][nt];
                    mma_fp16(d[0], d[1], d[2], d[3], a0, a1, a2, a3, bl[nt][0], bl[nt][1]);
                }
                #pragma unroll
                for (int nt = 0; nt < 4; nt++) {
                    float* d = acc[mt][nt];
                    mma_fp16(d[0], d[1], d[2], d[3], a0, a1, a2, a3, bh[nt][0], bh[nt][1]);
                }
            }
        }
        __syncthreads();
    }
    #undef PREFETCH3

    #pragma unroll
    for (int mt = 0; mt < 4; mt++) {
        const int row0 = rowBase + warp_m * 64 + mt * 16 + r;
        #pragma unroll
        for (int nt = 0; nt < 4; nt++) {
            const int col = colBase + warp_n * 32 + nt * 8 + 2 * cq;
            const float b0v = bias[col], b1v = bias[col + 1];
            float2 p0 = make_float2(acc[mt][nt][0] + b0v, acc[mt][nt][1] + b1v);
            float2 p1 = make_float2(acc[mt][nt][2] + b0v, acc[mt][nt][3] + b1v);
            *(float2*)&C[(size_t)row0 * Ncols + col]       = p0;
            *(float2*)&C[(size_t)(row0 + 8) * Ncols + col] = p1;
        }
    }
}

// ============================================================
// sigma: one warp per (b,n); each THREAD accumulates all 8 heads.
// ============================================================
__global__ __launch_bounds__(256)
void sigma_kernel(const float* __restrict__ x, const float4* __restrict__ Wsig,
                  const float* __restrict__ bsig, float* __restrict__ inv_out)
{
    const int warp = threadIdx.x >> 5;
    const int lane = threadIdx.x & 31;
    const int bn = blockIdx.x * 8 + warp;
    const int b = bn / N;
    const int n = bn % N;

    const float* xrow = x + (size_t)bn * D;
    float acc[HEADS];
    #pragma unroll
    for (int h = 0; h < HEADS; h++) acc[h] = 0.f;

    #pragma unroll
    for (int it = 0; it < D / 32; it++) {
        const int d = lane + 32 * it;
        const float xv = __ldg(&xrow[d]);
        const float4 w0 = __ldg(&Wsig[d * 2 + 0]);
        const float4 w1 = __ldg(&Wsig[d * 2 + 1]);
        acc[0] += xv * w0.x;  acc[1] += xv * w0.y;
        acc[2] += xv * w0.z;  acc[3] += xv * w0.w;
        acc[4] += xv * w1.x;  acc[5] += xv * w1.y;
        acc[6] += xv * w1.z;  acc[7] += xv * w1.w;
    }

    #pragma unroll
    for (int off = 16; off > 0; off >>= 1)
        #pragma unroll
        for (int h = 0; h < HEADS; h++)
            acc[h] += __shfl_xor_sync(0xFFFFFFFFu, acc[h], off);

    if (lane < HEADS) {
        const int h = lane;
        float s = acc[h] + __ldg(&bsig[h]);
        float sig = 1.f / (1.f + expf(-s));
        float denom = expf(sig) + 1.f;
        inv_out[((size_t)b * HEADS + h) * N + n] = 1.f / denom;
    }
}

// ============================================================
// Band kernel — f32x2 Horner, 8 rows/thread (256 threads):
// one LDS.64 feeds 8 fma2. Emits attn as single fp16 pair.
// g = tid>>5 (8 groups x 8 rows), lp = tid&31 (dh pair).
// ============================================================
__global__ __launch_bounds__(256)
void band_kernel(const float* __restrict__ v, const float* __restrict__ inv_arr,
                 unsigned short* __restrict__ a16)
{
    __shared__ float vs[RB + 2 * BW][DH];   // 192 x 64 = 48KB

    const int b  = blockIdx.z;
    const int h  = blockIdx.y;
    const int i0 = blockIdx.x * RB;
    const int tid = threadIdx.x;
    const int lp  = tid & 31;               // dh pair index
    const int g   = tid >> 5;               // 0..7, rows base g*8

    for (int t = tid; t < (RB + 2 * BW) * (DH / 4); t += 256) {
        const int row = t >> 4;
        const int c4  = (t & 15) * 4;
        const int jj  = i0 - BW + row;
        float4 val = make_float4(0.f, 0.f, 0.f, 0.f);
        if (jj >= 0 && jj < N)
            val = __ldg((const float4*)&v[((size_t)(b * N + jj)) * INNER + h * DH + c4]);
        *(float4*)&vs[row][c4] = val;
    }
    __syncthreads();

    const float* invp = inv_arr + ((size_t)b * HEADS + h) * N;
    const int base = i0 + g * 8;            // global row of t=0
    // local center of row t is (g*8 + t) + 64

    float rr[8], iv[8];
    uint64_t rr2[8], accL[8], accR[8];
    #pragma unroll
    for (int t = 0; t < 8; t++) {
        iv[t]   = invp[base + t];
        rr[t]   = __expf(-iv[t]);
        rr2[t]  = f32x2_pack(rr[t], rr[t]);
        accL[t] = 0ull;
        accR[t] = 0ull;
    }

    // ---- Left sweep: j ascending; row t active iff m <= 64+t (center incl).
    // Start jl=g*8 adds <=7 far terms (weight <= r^65 ~ 1e-9, true mass).
    {
        int jl = g * 8;
        #pragma unroll 8
        for (int m = 0; m < 65; m++) {
            const uint64_t v2 = *(const uint64_t*)&vs[jl][2 * lp];
            #pragma unroll
            for (int t = 0; t < 8; t++) accL[t] = fma2(accL[t], rr2[t], v2);
            jl++;
        }
        #pragma unroll
        for (int m = 65; m < 72; m++) {     // row t active iff t >= m-64
            const uint64_t v2 = *(const uint64_t*)&vs[jl][2 * lp];
            #pragma unroll
            for (int t = 0; t < 8; t++)
                if (t >= m - 64) accL[t] = fma2(accL[t], rr2[t], v2);
            jl++;
        }
    }

    // ---- Right sweep: j descending, row t window [center+1, center+64];
    // start jl=g*8+135 (row7 center+64); all rows active while m<64.
    {
        int jl = g * 8 + 135;
        #pragma unroll 8
        for (int m = 0; m < 64; m++) {
            const uint64_t v2 = *(const uint64_t*)&vs[jl][2 * lp];
            #pragma unroll
            for (int t = 0; t < 8; t++) accR[t] = fma2(accR[t], rr2[t], v2);
            jl--;
        }
        #pragma unroll
        for (int m = 64; m < 71; m++) {     // row t active iff t <= 70-m
            const uint64_t v2 = *(const uint64_t*)&vs[jl][2 * lp];
            #pragma unroll
            for (int t = 0; t < 8; t++)
                if (t <= 70 - m) accR[t] = fma2(accR[t], rr2[t], v2);
            jl--;
        }
    }

    // ---- combine, normalize (exact analytic Z), emit fp16 pair ----
    #pragma unroll
    for (int t = 0; t < 8; t++) {
        const int i = base + t;
        const float r_ = rr[t];
        const uint64_t sum2 = fma2(rr2[t], accR[t], accL[t]);   // accL + r*accR
        const float Z = (1.f - __expf(-(float)(i + 1) * iv[t])
                         + r_ - __expf(-(float)(N - i) * iv[t])) / (1.f - r_);
        const float zi = 1.f / Z;
        const float2 o = f32x2_unpack(mul2(sum2, f32x2_pack(zi, zi)));

        __half2 hp = __halves2half2(__float2half_rn(o.x), __float2half_rn(o.y));
        const size_t idx = ((size_t)(b * N + i)) * INNER + h * DH + 2 * lp;
        *(uint32_t*)&a16[idx] = *reinterpret_cast<uint32_t*>(&hp);
    }
}

// ============================================================
// Launch: x, W_v, W_sigma, b_sigma, W_out, b_out
// ============================================================
extern "C" void kernel_launch(void* const* d_in, const int* in_sizes, int n_in,
                              void* d_out, int out_size)
{
    const float* x     = (const float*)d_in[0];
    const float* W_v   = (const float*)d_in[1];
    const float* W_sig = (const float*)d_in[2];
    const float* b_sig = (const float*)d_in[3];
    const float* W_out = (const float*)d_in[4];
    const float* b_out = (const float*)d_in[5];
    float* out = (float*)d_out;

    uint32_t *xhi, *xlo, *wvt_hi, *wvt_lo, *wot_hi, *wot_lo;
    float *v, *inv;
    unsigned short *a16;
    cudaGetSymbolAddress((void**)&xhi, g_xhi);
    cudaGetSymbolAddress((void**)&xlo, g_xlo);
    cudaGetSymbolAddress((void**)&wvt_hi, g_wvt_hi);
    cudaGetSymbolAddress((void**)&wvt_lo, g_wvt_lo);
    cudaGetSymbolAddress((void**)&wot_hi, g_wot_hi);
    cudaGetSymbolAddress((void**)&wot_lo, g_wot_lo);
    cudaGetSymbolAddress((void**)&v, g_v);
    cudaGetSymbolAddress((void**)&inv, g_inv);
    cudaGetSymbolAddress((void**)&a16, g_a16);

    static bool attr_set = false;
    if (!attr_set) {
        cudaFuncSetAttribute(gemm_bf16x3_kernel,
                             cudaFuncAttributeMaxDynamicSharedMemorySize,
                             GEMM_SMEM_BYTES);
        cudaFuncSetAttribute(gemm_a16_kernel,
                             cudaFuncAttributeMaxDynamicSharedMemorySize,
                             GEMM3_SMEM_BYTES);
        attr_set = true;
    }

    // split x into bf16 hi/lo
    {
        const int n4 = M_ROWS * D / 4;
        convert_split_kernel<<<n4 / 256, 256>>>((const float4*)x, (uint2*)xhi, (uint2*)xlo, n4);
    }
    // transpose+split weights: W_v (bf16 x3 path), W_out (fp16 2-pass path)
    {
        dim3 grid(INNER / 32, D / 32);
        convert_wt_kernel<<<grid, 256>>>(W_v, wvt_hi, wvt_lo, D, INNER);
    }
    {
        dim3 grid(D / 32, INNER / 32);
        convert_wt_fp16_kernel<<<grid, 256>>>(W_out, wot_hi, wot_lo, INNER, D);
    }
    // v = x @ W_v  (bf16x3)
    {
        dim3 grid(INNER / 128, M_ROWS / 128);
        gemm_bf16x3_kernel<<<grid, 256, GEMM_SMEM_BYTES>>>(xhi, xlo, wvt_hi, wvt_lo,
                                                           nullptr, v, M_ROWS, INNER, D);
    }
    // sigma
    sigma_kernel<<<M_ROWS / 8, 256>>>(x, (const float4*)W_sig, b_sig, inv);
    // banded prior @ v -> attn fp16
    {
        dim3 grid(N / RB, HEADS, B);
        band_kernel<<<grid, 256>>>(v, inv, a16);
    }
    // out = attn @ W_out + b_out  (fp16 2-pass)
    {
        dim3 grid(D / 128, M_ROWS / 128);
        gemm_a16_kernel<<<grid, 256, GEMM3_SMEM_BYTES>>>((const uint32_t*)a16,
                                                         wot_hi, wot_lo, b_out, out,
                                                         D, INNER);
    }
}

// round 13
// speedup vs baseline: 4.1373x; 1.2549x over previous
#include <cuda_runtime.h>
#include <cuda_bf16.h>
#include <cuda_fp16.h>
#include <math.h>
#include <stdint.h>

// Problem constants
#define B     4
#define N     2048
#define D     512
#define HEADS 8
#define DH    64
#define INNER 512
#define M_ROWS (B*N)        // 8192
#define KU512  (512/2)      // 256 u32 (fp16 pairs) per row of K=512

// Band params
#define BW 64
#define RB 64

// GEMM smem geometry (u32 units)
#define ROWSTRIDE 20                    // 16 payload + 4 pad (ldmatrix conflict-free)
#define ARR_U32   (128 * ROWSTRIDE)     // 2560 u32 per array
// 2-pass kernel: 3 arrays per stage (A, Bhi, Blo)
#define STAGE3_U32 (3 * ARR_U32)        // 30KB per stage
#define GEMM3_SMEM_BYTES (2 * STAGE3_U32 * 4)  // 61440
// 1-pass kernel: 2 arrays per stage (A, B)
#define STAGE2_U32 (2 * ARR_U32)        // 20KB per stage
#define GEMM2_SMEM_BYTES (2 * STAGE2_U32 * 4)  // 40960

// ---------------- scratch (__device__ globals; no allocation) ----------------
__device__ uint32_t g_x16[M_ROWS * KU512];     // x fp16 pairs
__device__ uint32_t g_wvt_hi[INNER * KU512];   // W_v^T fp16 hi pairs
__device__ uint32_t g_wvt_lo[INNER * KU512];   // W_v^T fp16 lo pairs
__device__ uint32_t g_wot16[D * (INNER/2)];    // W_out^T fp16 single pairs
__device__ float    g_v[M_ROWS * INNER];
__device__ unsigned short g_a16[M_ROWS * INNER]; // attn fp16
__device__ float    g_inv[B*HEADS*N];

// ---------------- helpers ----------------
__device__ __forceinline__ void mma_fp16(float& d0, float& d1, float& d2, float& d3,
                                         uint32_t a0, uint32_t a1, uint32_t a2, uint32_t a3,
                                         uint32_t b0, uint32_t b1) {
    asm volatile(
        "mma.sync.aligned.m16n8k16.row.col.f32.f16.f16.f32 "
        "{%0,%1,%2,%3}, {%4,%5,%6,%7}, {%8,%9}, {%0,%1,%2,%3};\n"
        : "+f"(d0), "+f"(d1), "+f"(d2), "+f"(d3)
        : "r"(a0), "r"(a1), "r"(a2), "r"(a3), "r"(b0), "r"(b1));
}

__device__ __forceinline__ void ldsm_x4(uint32_t& r0, uint32_t& r1, uint32_t& r2, uint32_t& r3,
                                        uint32_t addr) {
    asm volatile("ldmatrix.sync.aligned.m8n8.x4.shared.b16 {%0,%1,%2,%3}, [%4];\n"
                 : "=r"(r0), "=r"(r1), "=r"(r2), "=r"(r3) : "r"(addr));
}

__device__ __forceinline__ void cp_async16(uint32_t* smem, const uint32_t* gmem) {
    uint32_t s = (uint32_t)__cvta_generic_to_shared(smem);
    asm volatile("cp.async.cg.shared.global [%0], [%1], 16;\n" :: "r"(s), "l"(gmem));
}
__device__ __forceinline__ void cp_commit() { asm volatile("cp.async.commit_group;\n"); }
__device__ __forceinline__ void cp_wait1()  { asm volatile("cp.async.wait_group 1;\n"); }
__device__ __forceinline__ void cp_wait0()  { asm volatile("cp.async.wait_group 0;\n"); }

// ---------------- packed f32x2 (Blackwell base ISA) ----------------
__device__ __forceinline__ uint64_t f32x2_pack(float lo, float hi) {
    float2 t = make_float2(lo, hi);
    return *reinterpret_cast<uint64_t*>(&t);
}
__device__ __forceinline__ float2 f32x2_unpack(uint64_t v) {
    return *reinterpret_cast<float2*>(&v);
}
__device__ __forceinline__ uint64_t fma2(uint64_t a, uint64_t b, uint64_t c) {
    uint64_t d;
    asm("fma.rn.f32x2 %0, %1, %2, %3;" : "=l"(d) : "l"(a), "l"(b), "l"(c));
    return d;
}
__device__ __forceinline__ uint64_t mul2(uint64_t a, uint64_t b) {
    uint64_t d;
    asm("mul.rn.f32x2 %0, %1, %2;" : "=l"(d) : "l"(a), "l"(b));
    return d;
}

// ============================================================
// convert_x16: fp32 -> fp16 RN pairs
// ============================================================
__global__ __launch_bounds__(256)
void convert_x16_kernel(const float4* __restrict__ in, uint2* __restrict__ out16, int n4)
{
    int i = blockIdx.x * blockDim.x + threadIdx.x;
    if (i >= n4) return;
    float4 v = in[i];
    __half2 p0 = __floats2half2_rn(v.x, v.y);   // v.x in low half
    __half2 p1 = __floats2half2_rn(v.z, v.w);
    uint2 o;
    o.x = *reinterpret_cast<uint32_t*>(&p0);
    o.y = *reinterpret_cast<uint32_t*>(&p1);
    out16[i] = o;
}

// ============================================================
// convert_wt_fp16: transpose W [K][Nc] fp32 -> fp16 hi/lo pairs [Nc][K/2]
// hi = rn_fp16(w), lo = rn_fp16(w - hi)
// ============================================================
__global__ __launch_bounds__(256)
void convert_wt_fp16_kernel(const float* __restrict__ W, uint32_t* __restrict__ Whi,
                            uint32_t* __restrict__ Wlo, int K, int Nc)
{
    __shared__ float s[32][33];
    const int k0 = blockIdx.y * 32, n0 = blockIdx.x * 32;
    const int tx = threadIdx.x & 31, ty = threadIdx.x >> 5;
    #pragma unroll
    for (int q = 0; q < 4; q++)
        s[ty + 8*q][tx] = W[(size_t)(k0 + ty + 8*q) * Nc + n0 + tx];
    __syncthreads();
    for (int o = threadIdx.x; o < 512; o += 256) {
        const int n  = o >> 4;
        const int kp = o & 15;
        float v0 = s[2*kp][n], v1 = s[2*kp + 1][n];
        __half h0 = __float2half_rn(v0), h1 = __float2half_rn(v1);
        __half l0 = __float2half_rn(v0 - __half2float(h0));
        __half l1 = __float2half_rn(v1 - __half2float(h1));
        __half2 hp = __halves2half2(h0, h1);
        __half2 lp = __halves2half2(l0, l1);
        size_t oi = (size_t)(n0 + n) * (K >> 1) + (k0 >> 1) + kp;
        Whi[oi] = *reinterpret_cast<uint32_t*>(&hp);
        Wlo[oi] = *reinterpret_cast<uint32_t*>(&lp);
    }
}

// ============================================================
// convert_wt_fp16s: transpose W [K][Nc] fp32 -> fp16 SINGLE pairs [Nc][K/2]
// ============================================================
__global__ __launch_bounds__(256)
void convert_wt_fp16s_kernel(const float* __restrict__ W, uint32_t* __restrict__ W16,
                             int K, int Nc)
{
    __shared__ float s[32][33];
    const int k0 = blockIdx.y * 32, n0 = blockIdx.x * 32;
    const int tx = threadIdx.x & 31, ty = threadIdx.x >> 5;
    #pragma unroll
    for (int q = 0; q < 4; q++)
        s[ty + 8*q][tx] = W[(size_t)(k0 + ty + 8*q) * Nc + n0 + tx];
    __syncthreads();
    for (int o = threadIdx.x; o < 512; o += 256) {
        const int n  = o >> 4;
        const int kp = o & 15;
        __half2 hp = __floats2half2_rn(s[2*kp][n], s[2*kp + 1][n]);
        size_t oi = (size_t)(n0 + n) * (K >> 1) + (k0 >> 1) + kp;
        W16[oi] = *reinterpret_cast<uint32_t*>(&hp);
    }
}

// ============================================================
// fp16 2-pass GEMM: C = A(fp16) @ [Bhi + Blo]^T (+bias if non-null)
// 3 smem arrays per stage. 2 mma passes per fragment.
// ============================================================
__global__ __launch_bounds__(256, 2)
void gemm_a16_kernel(const uint32_t* __restrict__ A16, const uint32_t* __restrict__ Bhi,
                     const uint32_t* __restrict__ Blo, const float* __restrict__ bias,
                     float* __restrict__ C, int Ncols, int K)
{
    extern __shared__ uint32_t smem[];
    const int KUr = K >> 1;
    const int ntiles = KUr >> 4;

    const int tid = threadIdx.x;
    const int wid = tid >> 5, lane = tid & 31;
    const int warp_m = wid & 1;
    const int warp_n = wid >> 1;
    const int r  = lane >> 2;
    const int cq = lane & 3;
    const int rowBase = blockIdx.y * 128;
    const int colBase = blockIdx.x * 128;

    const int cRow = tid >> 2;
    const int cQ4  = (tid & 3) * 4;

    const int aOffBase = (warp_m * 64 + (lane & 15)) * ROWSTRIDE + ((lane >> 4) << 2);
    const int bOffBase = (warp_n * 32 + (lane & 7) + ((lane >> 4) << 3)) * ROWSTRIDE
                         + (((lane >> 3) & 1) << 2);

    const uint32_t smem_base_addr = (uint32_t)__cvta_generic_to_shared(smem);

    #define PREFETCH3(kt, st) do {                                                    \
        uint32_t* s_ = smem + (st) * STAGE3_U32;                                      \
        _Pragma("unroll")                                                             \
        for (int half = 0; half < 2; half++) {                                        \
            const int rr_ = cRow + half * 64;                                         \
            const size_t ao_ = (size_t)(rowBase + rr_) * KUr + (kt) + cQ4;            \
            const size_t bo_ = (size_t)(colBase + rr_) * KUr + (kt) + cQ4;            \
            cp_async16(s_ + 0*ARR_U32 + rr_*ROWSTRIDE + cQ4, A16 + ao_);              \
            cp_async16(s_ + 1*ARR_U32 + rr_*ROWSTRIDE + cQ4, Bhi + bo_);              \
            cp_async16(s_ + 2*ARR_U32 + rr_*ROWSTRIDE + cQ4, Blo + bo_);              \
        }                                                                             \
    } while (0)

    float acc[4][4][4];
    #pragma unroll
    for (int a = 0; a < 4; a++)
        #pragma unroll
        for (int b_ = 0; b_ < 4; b_++)
            #pragma unroll
            for (int c = 0; c < 4; c++) acc[a][b_][c] = 0.f;

    PREFETCH3(0, 0);
    cp_commit();

    for (int t = 0; t < ntiles; t++) {
        if (t + 1 < ntiles) {
            PREFETCH3((t + 1) * 16, (t + 1) & 1);
            cp_commit();
            cp_wait1();
        } else {
            cp_wait0();
        }
        __syncthreads();

        const uint32_t stage = smem_base_addr + ((t & 1) * STAGE3_U32) * 4;
        const uint32_t aB   = stage + (0 * ARR_U32 + aOffBase) * 4;
        const uint32_t bHiB = stage + (1 * ARR_U32 + bOffBase) * 4;
        const uint32_t bLoB = stage + (2 * ARR_U32 + bOffBase) * 4;

        #pragma unroll
        for (int ks = 0; ks < 2; ks++) {
            const uint32_t kuB = ks * 8 * 4;
            uint32_t bh[4][2], bl[4][2];
            #pragma unroll
            for (int pair = 0; pair < 2; pair++) {
                const uint32_t po = pair * 16 * ROWSTRIDE * 4;
                ldsm_x4(bh[2*pair][0], bh[2*pair][1], bh[2*pair+1][0], bh[2*pair+1][1],
                        bHiB + po + kuB);
                ldsm_x4(bl[2*pair][0], bl[2*pair][1], bl[2*pair+1][0], bl[2*pair+1][1],
                        bLoB + po + kuB);
            }
            #pragma unroll
            for (int mt = 0; mt < 4; mt++) {
                const uint32_t mo = mt * 16 * ROWSTRIDE * 4;
                uint32_t a0, a1, a2, a3;
                ldsm_x4(a0, a1, a2, a3, aB + mo + kuB);
                #pragma unroll
                for (int nt = 0; nt < 4; nt++) {
                    float* d = acc[mt][nt];
                    mma_fp16(d[0], d[1], d[2], d[3], a0, a1, a2, a3, bl[nt][0], bl[nt][1]);
                }
                #pragma unroll
                for (int nt = 0; nt < 4; nt++) {
                    float* d = acc[mt][nt];
                    mma_fp16(d[0], d[1], d[2], d[3], a0, a1, a2, a3, bh[nt][0], bh[nt][1]);
                }
            }
        }
        __syncthreads();
    }
    #undef PREFETCH3

    #pragma unroll
    for (int mt = 0; mt < 4; mt++) {
        const int row0 = rowBase + warp_m * 64 + mt * 16 + r;
        #pragma unroll
        for (int nt = 0; nt < 4; nt++) {
            const int col = colBase + warp_n * 32 + nt * 8 + 2 * cq;
            float b0v = 0.f, b1v = 0.f;
            if (bias) { b0v = bias[col]; b1v = bias[col + 1]; }
            float2 p0 = make_float2(acc[mt][nt][0] + b0v, acc[mt][nt][1] + b1v);
            float2 p1 = make_float2(acc[mt][nt][2] + b0v, acc[mt][nt][3] + b1v);
            *(float2*)&C[(size_t)row0 * Ncols + col]       = p0;
            *(float2*)&C[(size_t)(row0 + 8) * Ncols + col] = p1;
        }
    }
}

// ============================================================
// fp16 1-pass GEMM: C = A(fp16) @ B16^T + bias.
// 2 smem arrays per stage. 1 mma pass per fragment.
// ============================================================
__global__ __launch_bounds__(256, 2)
void gemm_a16_1p_kernel(const uint32_t* __restrict__ A16, const uint32_t* __restrict__ B16,
                        const float* __restrict__ bias, float* __restrict__ C,
                        int Ncols, int K)
{
    extern __shared__ uint32_t smem[];
    const int KUr = K >> 1;
    const int ntiles = KUr >> 4;

    const int tid = threadIdx.x;
    const int wid = tid >> 5, lane = tid & 31;
    const int warp_m = wid & 1;
    const int warp_n = wid >> 1;
    const int r  = lane >> 2;
    const int cq = lane & 3;
    const int rowBase = blockIdx.y * 128;
    const int colBase = blockIdx.x * 128;

    const int cRow = tid >> 2;
    const int cQ4  = (tid & 3) * 4;

    const int aOffBase = (warp_m * 64 + (lane & 15)) * ROWSTRIDE + ((lane >> 4) << 2);
    const int bOffBase = (warp_n * 32 + (lane & 7) + ((lane >> 4) << 3)) * ROWSTRIDE
                         + (((lane >> 3) & 1) << 2);

    const uint32_t smem_base_addr = (uint32_t)__cvta_generic_to_shared(smem);

    #define PREFETCH2(kt, st) do {                                                    \
        uint32_t* s_ = smem + (st) * STAGE2_U32;                                      \
        _Pragma("unroll")                                                             \
        for (int half = 0; half < 2; half++) {                                        \
            const int rr_ = cRow + half * 64;                                         \
            const size_t ao_ = (size_t)(rowBase + rr_) * KUr + (kt) + cQ4;            \
            const size_t bo_ = (size_t)(colBase + rr_) * KUr + (kt) + cQ4;            \
            cp_async16(s_ + 0*ARR_U32 + rr_*ROWSTRIDE + cQ4, A16 + ao_);              \
            cp_async16(s_ + 1*ARR_U32 + rr_*ROWSTRIDE + cQ4, B16 + bo_);              \
        }                                                                             \
    } while (0)

    float acc[4][4][4];
    #pragma unroll
    for (int a = 0; a < 4; a++)
        #pragma unroll
        for (int b_ = 0; b_ < 4; b_++)
            #pragma unroll
            for (int c = 0; c < 4; c++) acc[a][b_][c] = 0.f;

    PREFETCH2(0, 0);
    cp_commit();

    for (int t = 0; t < ntiles; t++) {
        if (t + 1 < ntiles) {
            PREFETCH2((t + 1) * 16, (t + 1) & 1);
            cp_commit();
            cp_wait1();
        } else {
            cp_wait0();
        }
        __syncthreads();

        const uint32_t stage = smem_base_addr + ((t & 1) * STAGE2_U32) * 4;
        const uint32_t aB  = stage + (0 * ARR_U32 + aOffBase) * 4;
        const uint32_t bB  = stage + (1 * ARR_U32 + bOffBase) * 4;

        #pragma unroll
        for (int ks = 0; ks < 2; ks++) {
            const uint32_t kuB = ks * 8 * 4;
            uint32_t bh[4][2];
            #pragma unroll
            for (int pair = 0; pair < 2; pair++) {
                const uint32_t po = pair * 16 * ROWSTRIDE * 4;
                ldsm_x4(bh[2*pair][0], bh[2*pair][1], bh[2*pair+1][0], bh[2*pair+1][1],
                        bB + po + kuB);
            }
            #pragma unroll
            for (int mt = 0; mt < 4; mt++) {
                const uint32_t mo = mt * 16 * ROWSTRIDE * 4;
                uint32_t a0, a1, a2, a3;
                ldsm_x4(a0, a1, a2, a3, aB + mo + kuB);
                #pragma unroll
                for (int nt = 0; nt < 4; nt++) {
                    float* d = acc[mt][nt];
                    mma_fp16(d[0], d[1], d[2], d[3], a0, a1, a2, a3, bh[nt][0], bh[nt][1]);
                }
            }
        }
        __syncthreads();
    }
    #undef PREFETCH2

    #pragma unroll
    for (int mt = 0; mt < 4; mt++) {
        const int row0 = rowBase + warp_m * 64 + mt * 16 + r;
        #pragma unroll
        for (int nt = 0; nt < 4; nt++) {
            const int col = colBase + warp_n * 32 + nt * 8 + 2 * cq;
            const float b0v = bias[col], b1v = bias[col + 1];
            float2 p0 = make_float2(acc[mt][nt][0] + b0v, acc[mt][nt][1] + b1v);
            float2 p1 = make_float2(acc[mt][nt][2] + b0v, acc[mt][nt][3] + b1v);
            *(float2*)&C[(size_t)row0 * Ncols + col]       = p0;
            *(float2*)&C[(size_t)(row0 + 8) * Ncols + col] = p1;
        }
    }
}

// ============================================================
// sigma: one warp per (b,n); each THREAD accumulates all 8 heads.
// ============================================================
__global__ __launch_bounds__(256)
void sigma_kernel(const float* __restrict__ x, const float4* __restrict__ Wsig,
                  const float* __restrict__ bsig, float* __restrict__ inv_out)
{
    const int warp = threadIdx.x >> 5;
    const int lane = threadIdx.x & 31;
    const int bn = blockIdx.x * 8 + warp;
    const int b = bn / N;
    const int n = bn % N;

    const float* xrow = x + (size_t)bn * D;
    float acc[HEADS];
    #pragma unroll
    for (int h = 0; h < HEADS; h++) acc[h] = 0.f;

    #pragma unroll
    for (int it = 0; it < D / 32; it++) {
        const int d = lane + 32 * it;
        const float xv = __ldg(&xrow[d]);
        const float4 w0 = __ldg(&Wsig[d * 2 + 0]);
        const float4 w1 = __ldg(&Wsig[d * 2 + 1]);
        acc[0] += xv * w0.x;  acc[1] += xv * w0.y;
        acc[2] += xv * w0.z;  acc[3] += xv * w0.w;
        acc[4] += xv * w1.x;  acc[5] += xv * w1.y;
        acc[6] += xv * w1.z;  acc[7] += xv * w1.w;
    }

    #pragma unroll
    for (int off = 16; off > 0; off >>= 1)
        #pragma unroll
        for (int h = 0; h < HEADS; h++)
            acc[h] += __shfl_xor_sync(0xFFFFFFFFu, acc[h], off);

    if (lane < HEADS) {
        const int h = lane;
        float s = acc[h] + __ldg(&bsig[h]);
        float sig = 1.f / (1.f + expf(-s));
        float denom = expf(sig) + 1.f;
        inv_out[((size_t)b * HEADS + h) * N + n] = 1.f / denom;
    }
}

// ============================================================
// Band kernel — f32x2 Horner, 8 rows/thread (256 threads):
// one LDS.64 feeds 8 fma2. Emits attn as fp16 pair.
// ============================================================
__global__ __launch_bounds__(256)
void band_kernel(const float* __restrict__ v, const float* __restrict__ inv_arr,
                 unsigned short* __restrict__ a16)
{
    __shared__ float vs[RB + 2 * BW][DH];   // 192 x 64 = 48KB

    const int b  = blockIdx.z;
    const int h  = blockIdx.y;
    const int i0 = blockIdx.x * RB;
    const int tid = threadIdx.x;
    const int lp  = tid & 31;               // dh pair index
    const int g   = tid >> 5;               // 0..7, rows base g*8

    for (int t = tid; t < (RB + 2 * BW) * (DH / 4); t += 256) {
        const int row = t >> 4;
        const int c4  = (t & 15) * 4;
        const int jj  = i0 - BW + row;
        float4 val = make_float4(0.f, 0.f, 0.f, 0.f);
        if (jj >= 0 && jj < N)
            val = __ldg((const float4*)&v[((size_t)(b * N + jj)) * INNER + h * DH + c4]);
        *(float4*)&vs[row][c4] = val;
    }
    __syncthreads();

    const float* invp = inv_arr + ((size_t)b * HEADS + h) * N;
    const int base = i0 + g * 8;

    float rr[8], iv[8];
    uint64_t rr2[8], accL[8], accR[8];
    #pragma unroll
    for (int t = 0; t < 8; t++) {
        iv[t]   = invp[base + t];
        rr[t]   = __expf(-iv[t]);
        rr2[t]  = f32x2_pack(rr[t], rr[t]);
        accL[t] = 0ull;
        accR[t] = 0ull;
    }

    // Left sweep: j ascending; center included.
    {
        int jl = g * 8;
        #pragma unroll 8
        for (int m = 0; m < 65; m++) {
            const uint64_t v2 = *(const uint64_t*)&vs[jl][2 * lp];
            #pragma unroll
            for (int t = 0; t < 8; t++) accL[t] = fma2(accL[t], rr2[t], v2);
            jl++;
        }
        #pragma unroll
        for (int m = 65; m < 72; m++) {
            const uint64_t v2 = *(const uint64_t*)&vs[jl][2 * lp];
            #pragma unroll
            for (int t = 0; t < 8; t++)
                if (t >= m - 64) accL[t] = fma2(accL[t], rr2[t], v2);
            jl++;
        }
    }

    // Right sweep: j descending, windows [center+1, center+64].
    {
        int jl = g * 8 + 135;
        #pragma unroll 8
        for (int m = 0; m < 64; m++) {
            const uint64_t v2 = *(const uint64_t*)&vs[jl][2 * lp];
            #pragma unroll
            for (int t = 0; t < 8; t++) accR[t] = fma2(accR[t], rr2[t], v2);
            jl--;
        }
        #pragma unroll
        for (int m = 64; m < 71; m++) {
            const uint64_t v2 = *(const uint64_t*)&vs[jl][2 * lp];
            #pragma unroll
            for (int t = 0; t < 8; t++)
                if (t <= 70 - m) accR[t] = fma2(accR[t], rr2[t], v2);
            jl--;
        }
    }

    // combine, normalize (exact analytic Z), emit fp16 pair
    #pragma unroll
    for (int t = 0; t < 8; t++) {
        const int i = base + t;
        const float r_ = rr[t];
        const uint64_t sum2 = fma2(rr2[t], accR[t], accL[t]);
        const float Z = (1.f - __expf(-(float)(i + 1) * iv[t])
                         + r_ - __expf(-(float)(N - i) * iv[t])) / (1.f - r_);
        const float zi = 1.f / Z;
        const float2 o = f32x2_unpack(mul2(sum2, f32x2_pack(zi, zi)));

        __half2 hp = __halves2half2(__float2half_rn(o.x), __float2half_rn(o.y));
        const size_t idx = ((size_t)(b * N + i)) * INNER + h * DH + 2 * lp;
        *(uint32_t*)&a16[idx] = *reinterpret_cast<uint32_t*>(&hp);
    }
}

// ============================================================
// Launch: x, W_v, W_sigma, b_sigma, W_out, b_out
// ============================================================
extern "C" void kernel_launch(void* const* d_in, const int* in_sizes, int n_in,
                              void* d_out, int out_size)
{
    const float* x     = (const float*)d_in[0];
    const float* W_v   = (const float*)d_in[1];
    const float* W_sig = (const float*)d_in[2];
    const float* b_sig = (const float*)d_in[3];
    const float* W_out = (const float*)d_in[4];
    const float* b_out = (const float*)d_in[5];
    float* out = (float*)d_out;

    uint32_t *x16, *wvt_hi, *wvt_lo, *wot16;
    float *v, *inv;
    unsigned short *a16;
    cudaGetSymbolAddress((void**)&x16, g_x16);
    cudaGetSymbolAddress((void**)&wvt_hi, g_wvt_hi);
    cudaGetSymbolAddress((void**)&wvt_lo, g_wvt_lo);
    cudaGetSymbolAddress((void**)&wot16, g_wot16);
    cudaGetSymbolAddress((void**)&v, g_v);
    cudaGetSymbolAddress((void**)&inv, g_inv);
    cudaGetSymbolAddress((void**)&a16, g_a16);

    static bool attr_set = false;
    if (!attr_set) {
        cudaFuncSetAttribute(gemm_a16_kernel,
                             cudaFuncAttributeMaxDynamicSharedMemorySize,
                             GEMM3_SMEM_BYTES);
        cudaFuncSetAttribute(gemm_a16_1p_kernel,
                             cudaFuncAttributeMaxDynamicSharedMemorySize,
                             GEMM2_SMEM_BYTES);
        attr_set = true;
    }

    // x -> fp16 pairs
    {
        const int n4 = M_ROWS * D / 4;
        convert_x16_kernel<<<n4 / 256, 256>>>((const float4*)x, (uint2*)x16, n4);
    }
    // W_v^T -> fp16 hi/lo ; W_out^T -> fp16 single
    {
        dim3 grid(INNER / 32, D / 32);
        convert_wt_fp16_kernel<<<grid, 256>>>(W_v, wvt_hi, wvt_lo, D, INNER);
    }
    {
        dim3 grid(D / 32, INNER / 32);
        convert_wt_fp16s_kernel<<<grid, 256>>>(W_out, wot16, INNER, D);
    }
    // v = x @ W_v  (fp16 2-pass)
    {
        dim3 grid(INNER / 128, M_ROWS / 128);
        gemm_a16_kernel<<<grid, 256, GEMM3_SMEM_BYTES>>>(x16, wvt_hi, wvt_lo,
                                                         nullptr, v, INNER, D);
    }
    // sigma
    sigma_kernel<<<M_ROWS / 8, 256>>>(x, (const float4*)W_sig, b_sig, inv);
    // banded prior @ v -> attn fp16
    {
        dim3 grid(N / RB, HEADS, B);
        band_kernel<<<grid, 256>>>(v, inv, a16);
    }
    // out = attn @ W_out + b_out  (fp16 1-pass)
    {
        dim3 grid(D / 128, M_ROWS / 128);
        gemm_a16_1p_kernel<<<grid, 256, GEMM2_SMEM_BYTES>>>((const uint32_t*)a16,
                                                            wot16, b_out, out,
                                                            D, INNER);
    }
}

// round 14
// speedup vs baseline: 4.5885x; 1.1091x over previous
#include <cuda_runtime.h>
#include <cuda_bf16.h>
#include <cuda_fp16.h>
#include <math.h>
#include <stdint.h>

// Problem constants
#define B     4
#define N     2048
#define D     512
#define HEADS 8
#define DH    64
#define INNER 512
#define M_ROWS (B*N)        // 8192
#define KU512  (512/2)      // 256 u32 (fp16 pairs) per row of K=512

// Band params
#define BW 64
#define RB 64

// GEMM smem geometry (u32 units)
#define ROWSTRIDE 20                    // 16 payload + 4 pad (ldmatrix conflict-free)
#define ARR_U32   (128 * ROWSTRIDE)     // 2560 u32 per array
// 1-pass kernel: 2 arrays per stage (A, B)
#define STAGE2_U32 (2 * ARR_U32)        // 20KB per stage
#define GEMM2_SMEM_BYTES (2 * STAGE2_U32 * 4)  // 40960

// ---------------- scratch (__device__ globals; no allocation) ----------------
__device__ uint32_t g_x16[M_ROWS * KU512];     // x fp16 pairs
__device__ uint32_t g_wvt16[INNER * KU512];    // W_v^T fp16 pairs
__device__ uint32_t g_wot16[D * (INNER/2)];    // W_out^T fp16 pairs
__device__ float    g_v[M_ROWS * INNER];
__device__ unsigned short g_a16[M_ROWS * INNER]; // attn fp16
__device__ float    g_inv[B*HEADS*N];

// ---------------- helpers ----------------
__device__ __forceinline__ void mma_fp16(float& d0, float& d1, float& d2, float& d3,
                                         uint32_t a0, uint32_t a1, uint32_t a2, uint32_t a3,
                                         uint32_t b0, uint32_t b1) {
    asm volatile(
        "mma.sync.aligned.m16n8k16.row.col.f32.f16.f16.f32 "
        "{%0,%1,%2,%3}, {%4,%5,%6,%7}, {%8,%9}, {%0,%1,%2,%3};\n"
        : "+f"(d0), "+f"(d1), "+f"(d2), "+f"(d3)
        : "r"(a0), "r"(a1), "r"(a2), "r"(a3), "r"(b0), "r"(b1));
}

__device__ __forceinline__ void ldsm_x4(uint32_t& r0, uint32_t& r1, uint32_t& r2, uint32_t& r3,
                                        uint32_t addr) {
    asm volatile("ldmatrix.sync.aligned.m8n8.x4.shared.b16 {%0,%1,%2,%3}, [%4];\n"
                 : "=r"(r0), "=r"(r1), "=r"(r2), "=r"(r3) : "r"(addr));
}

__device__ __forceinline__ void cp_async16(uint32_t* smem, const uint32_t* gmem) {
    uint32_t s = (uint32_t)__cvta_generic_to_shared(smem);
    asm volatile("cp.async.cg.shared.global [%0], [%1], 16;\n" :: "r"(s), "l"(gmem));
}
__device__ __forceinline__ void cp_commit() { asm volatile("cp.async.commit_group;\n"); }
__device__ __forceinline__ void cp_wait1()  { asm volatile("cp.async.wait_group 1;\n"); }
__device__ __forceinline__ void cp_wait0()  { asm volatile("cp.async.wait_group 0;\n"); }

// ---------------- packed f32x2 (Blackwell base ISA) ----------------
__device__ __forceinline__ uint64_t f32x2_pack(float lo, float hi) {
    float2 t = make_float2(lo, hi);
    return *reinterpret_cast<uint64_t*>(&t);
}
__device__ __forceinline__ float2 f32x2_unpack(uint64_t v) {
    return *reinterpret_cast<float2*>(&v);
}
__device__ __forceinline__ uint64_t fma2(uint64_t a, uint64_t b, uint64_t c) {
    uint64_t d;
    asm("fma.rn.f32x2 %0, %1, %2, %3;" : "=l"(d) : "l"(a), "l"(b), "l"(c));
    return d;
}
__device__ __forceinline__ uint64_t mul2(uint64_t a, uint64_t b) {
    uint64_t d;
    asm("mul.rn.f32x2 %0, %1, %2;" : "=l"(d) : "l"(a), "l"(b));
    return d;
}

// ============================================================
// convert_x16: fp32 -> fp16 RN pairs
// ============================================================
__global__ __launch_bounds__(256)
void convert_x16_kernel(const float4* __restrict__ in, uint2* __restrict__ out16, int n4)
{
    int i = blockIdx.x * blockDim.x + threadIdx.x;
    if (i >= n4) return;
    float4 v = in[i];
    __half2 p0 = __floats2half2_rn(v.x, v.y);   // v.x in low half
    __half2 p1 = __floats2half2_rn(v.z, v.w);
    uint2 o;
    o.x = *reinterpret_cast<uint32_t*>(&p0);
    o.y = *reinterpret_cast<uint32_t*>(&p1);
    out16[i] = o;
}

// ============================================================
// convert_wt_fp16s: transpose W [K][Nc] fp32 -> fp16 pairs [Nc][K/2]
// ============================================================
__global__ __launch_bounds__(256)
void convert_wt_fp16s_kernel(const float* __restrict__ W, uint32_t* __restrict__ W16,
                             int K, int Nc)
{
    __shared__ float s[32][33];
    const int k0 = blockIdx.y * 32, n0 = blockIdx.x * 32;
    const int tx = threadIdx.x & 31, ty = threadIdx.x >> 5;
    #pragma unroll
    for (int q = 0; q < 4; q++)
        s[ty + 8*q][tx] = W[(size_t)(k0 + ty + 8*q) * Nc + n0 + tx];
    __syncthreads();
    for (int o = threadIdx.x; o < 512; o += 256) {
        const int n  = o >> 4;
        const int kp = o & 15;
        __half2 hp = __floats2half2_rn(s[2*kp][n], s[2*kp + 1][n]);
        size_t oi = (size_t)(n0 + n) * (K >> 1) + (k0 >> 1) + kp;
        W16[oi] = *reinterpret_cast<uint32_t*>(&hp);
    }
}

// ============================================================
// fp16 1-pass GEMM: C = A(fp16) @ B16^T (+bias if non-null).
// 2 smem arrays per stage, 2-stage cp.async, ldmatrix fragments.
// ============================================================
__global__ __launch_bounds__(256, 2)
void gemm_a16_1p_kernel(const uint32_t* __restrict__ A16, const uint32_t* __restrict__ B16,
                        const float* __restrict__ bias, float* __restrict__ C,
                        int Ncols, int K)
{
    extern __shared__ uint32_t smem[];
    const int KUr = K >> 1;
    const int ntiles = KUr >> 4;

    const int tid = threadIdx.x;
    const int wid = tid >> 5, lane = tid & 31;
    const int warp_m = wid & 1;
    const int warp_n = wid >> 1;
    const int r  = lane >> 2;
    const int cq = lane & 3;
    const int rowBase = blockIdx.y * 128;
    const int colBase = blockIdx.x * 128;

    const int cRow = tid >> 2;
    const int cQ4  = (tid & 3) * 4;

    const int aOffBase = (warp_m * 64 + (lane & 15)) * ROWSTRIDE + ((lane >> 4) << 2);
    const int bOffBase = (warp_n * 32 + (lane & 7) + ((lane >> 4) << 3)) * ROWSTRIDE
                         + (((lane >> 3) & 1) << 2);

    const uint32_t smem_base_addr = (uint32_t)__cvta_generic_to_shared(smem);

    #define PREFETCH2(kt, st) do {                                                    \
        uint32_t* s_ = smem + (st) * STAGE2_U32;                                      \
        _Pragma("unroll")                                                             \
        for (int half = 0; half < 2; half++) {                                        \
            const int rr_ = cRow + half * 64;                                         \
            const size_t ao_ = (size_t)(rowBase + rr_) * KUr + (kt) + cQ4;            \
            const size_t bo_ = (size_t)(colBase + rr_) * KUr + (kt) + cQ4;            \
            cp_async16(s_ + 0*ARR_U32 + rr_*ROWSTRIDE + cQ4, A16 + ao_);              \
            cp_async16(s_ + 1*ARR_U32 + rr_*ROWSTRIDE + cQ4, B16 + bo_);              \
        }                                                                             \
    } while (0)

    float acc[4][4][4];
    #pragma unroll
    for (int a = 0; a < 4; a++)
        #pragma unroll
        for (int b_ = 0; b_ < 4; b_++)
            #pragma unroll
            for (int c = 0; c < 4; c++) acc[a][b_][c] = 0.f;

    PREFETCH2(0, 0);
    cp_commit();

    for (int t = 0; t < ntiles; t++) {
        if (t + 1 < ntiles) {
            PREFETCH2((t + 1) * 16, (t + 1) & 1);
            cp_commit();
            cp_wait1();
        } else {
            cp_wait0();
        }
        __syncthreads();

        const uint32_t stage = smem_base_addr + ((t & 1) * STAGE2_U32) * 4;
        const uint32_t aB  = stage + (0 * ARR_U32 + aOffBase) * 4;
        const uint32_t bB  = stage + (1 * ARR_U32 + bOffBase) * 4;

        #pragma unroll
        for (int ks = 0; ks < 2; ks++) {
            const uint32_t kuB = ks * 8 * 4;
            uint32_t bh[4][2];
            #pragma unroll
            for (int pair = 0; pair < 2; pair++) {
                const uint32_t po = pair * 16 * ROWSTRIDE * 4;
                ldsm_x4(bh[2*pair][0], bh[2*pair][1], bh[2*pair+1][0], bh[2*pair+1][1],
                        bB + po + kuB);
            }
            #pragma unroll
            for (int mt = 0; mt < 4; mt++) {
                const uint32_t mo = mt * 16 * ROWSTRIDE * 4;
                uint32_t a0, a1, a2, a3;
                ldsm_x4(a0, a1, a2, a3, aB + mo + kuB);
                #pragma unroll
                for (int nt = 0; nt < 4; nt++) {
                    float* d = acc[mt][nt];
                    mma_fp16(d[0], d[1], d[2], d[3], a0, a1, a2, a3, bh[nt][0], bh[nt][1]);
                }
            }
        }
        __syncthreads();
    }
    #undef PREFETCH2

    #pragma unroll
    for (int mt = 0; mt < 4; mt++) {
        const int row0 = rowBase + warp_m * 64 + mt * 16 + r;
        #pragma unroll
        for (int nt = 0; nt < 4; nt++) {
            const int col = colBase + warp_n * 32 + nt * 8 + 2 * cq;
            float b0v = 0.f, b1v = 0.f;
            if (bias) { b0v = bias[col]; b1v = bias[col + 1]; }
            float2 p0 = make_float2(acc[mt][nt][0] + b0v, acc[mt][nt][1] + b1v);
            float2 p1 = make_float2(acc[mt][nt][2] + b0v, acc[mt][nt][3] + b1v);
            *(float2*)&C[(size_t)row0 * Ncols + col]       = p0;
            *(float2*)&C[(size_t)(row0 + 8) * Ncols + col] = p1;
        }
    }
}

// ============================================================
// sigma: one warp per (b,n); each THREAD accumulates all 8 heads.
// ============================================================
__global__ __launch_bounds__(256)
void sigma_kernel(const float* __restrict__ x, const float4* __restrict__ Wsig,
                  const float* __restrict__ bsig, float* __restrict__ inv_out)
{
    const int warp = threadIdx.x >> 5;
    const int lane = threadIdx.x & 31;
    const int bn = blockIdx.x * 8 + warp;
    const int b = bn / N;
    const int n = bn % N;

    const float* xrow = x + (size_t)bn * D;
    float acc[HEADS];
    #pragma unroll
    for (int h = 0; h < HEADS; h++) acc[h] = 0.f;

    #pragma unroll
    for (int it = 0; it < D / 32; it++) {
        const int d = lane + 32 * it;
        const float xv = __ldg(&xrow[d]);
        const float4 w0 = __ldg(&Wsig[d * 2 + 0]);
        const float4 w1 = __ldg(&Wsig[d * 2 + 1]);
        acc[0] += xv * w0.x;  acc[1] += xv * w0.y;
        acc[2] += xv * w0.z;  acc[3] += xv * w0.w;
        acc[4] += xv * w1.x;  acc[5] += xv * w1.y;
        acc[6] += xv * w1.z;  acc[7] += xv * w1.w;
    }

    #pragma unroll
    for (int off = 16; off > 0; off >>= 1)
        #pragma unroll
        for (int h = 0; h < HEADS; h++)
            acc[h] += __shfl_xor_sync(0xFFFFFFFFu, acc[h], off);

    if (lane < HEADS) {
        const int h = lane;
        float s = acc[h] + __ldg(&bsig[h]);
        float sig = 1.f / (1.f + expf(-s));
        float denom = expf(sig) + 1.f;
        inv_out[((size_t)b * HEADS + h) * N + n] = 1.f / denom;
    }
}

// ============================================================
// Band kernel — f32x2 Horner, 8 rows/thread (256 threads):
// one LDS.64 feeds 8 fma2. Emits attn as fp16 pair.
// ============================================================
__global__ __launch_bounds__(256)
void band_kernel(const float* __restrict__ v, const float* __restrict__ inv_arr,
                 unsigned short* __restrict__ a16)
{
    __shared__ float vs[RB + 2 * BW][DH];   // 192 x 64 = 48KB

    const int b  = blockIdx.z;
    const int h  = blockIdx.y;
    const int i0 = blockIdx.x * RB;
    const int tid = threadIdx.x;
    const int lp  = tid & 31;               // dh pair index
    const int g   = tid >> 5;               // 0..7, rows base g*8

    for (int t = tid; t < (RB + 2 * BW) * (DH / 4); t += 256) {
        const int row = t >> 4;
        const int c4  = (t & 15) * 4;
        const int jj  = i0 - BW + row;
        float4 val = make_float4(0.f, 0.f, 0.f, 0.f);
        if (jj >= 0 && jj < N)
            val = __ldg((const float4*)&v[((size_t)(b * N + jj)) * INNER + h * DH + c4]);
        *(float4*)&vs[row][c4] = val;
    }
    __syncthreads();

    const float* invp = inv_arr + ((size_t)b * HEADS + h) * N;
    const int base = i0 + g * 8;

    float rr[8], iv[8];
    uint64_t rr2[8], accL[8], accR[8];
    #pragma unroll
    for (int t = 0; t < 8; t++) {
        iv[t]   = invp[base + t];
        rr[t]   = __expf(-iv[t]);
        rr2[t]  = f32x2_pack(rr[t], rr[t]);
        accL[t] = 0ull;
        accR[t] = 0ull;
    }

    // Left sweep: j ascending; center included.
    {
        int jl = g * 8;
        #pragma unroll 8
        for (int m = 0; m < 65; m++) {
            const uint64_t v2 = *(const uint64_t*)&vs[jl][2 * lp];
            #pragma unroll
            for (int t = 0; t < 8; t++) accL[t] = fma2(accL[t], rr2[t], v2);
            jl++;
        }
        #pragma unroll
        for (int m = 65; m < 72; m++) {
            const uint64_t v2 = *(const uint64_t*)&vs[jl][2 * lp];
            #pragma unroll
            for (int t = 0; t < 8; t++)
                if (t >= m - 64) accL[t] = fma2(accL[t], rr2[t], v2);
            jl++;
        }
    }

    // Right sweep: j descending, windows [center+1, center+64].
    {
        int jl = g * 8 + 135;
        #pragma unroll 8
        for (int m = 0; m < 64; m++) {
            const uint64_t v2 = *(const uint64_t*)&vs[jl][2 * lp];
            #pragma unroll
            for (int t = 0; t < 8; t++) accR[t] = fma2(accR[t], rr2[t], v2);
            jl--;
        }
        #pragma unroll
        for (int m = 64; m < 71; m++) {
            const uint64_t v2 = *(const uint64_t*)&vs[jl][2 * lp];
            #pragma unroll
            for (int t = 0; t < 8; t++)
                if (t <= 70 - m) accR[t] = fma2(accR[t], rr2[t], v2);
            jl--;
        }
    }

    // combine, normalize (exact analytic Z), emit fp16 pair
    #pragma unroll
    for (int t = 0; t < 8; t++) {
        const int i = base + t;
        const float r_ = rr[t];
        const uint64_t sum2 = fma2(rr2[t], accR[t], accL[t]);
        const float Z = (1.f - __expf(-(float)(i + 1) * iv[t])
                         + r_ - __expf(-(float)(N - i) * iv[t])) / (1.f - r_);
        const float zi = 1.f / Z;
        const float2 o = f32x2_unpack(mul2(sum2, f32x2_pack(zi, zi)));

        __half2 hp = __halves2half2(__float2half_rn(o.x), __float2half_rn(o.y));
        const size_t idx = ((size_t)(b * N + i)) * INNER + h * DH + 2 * lp;
        *(uint32_t*)&a16[idx] = *reinterpret_cast<uint32_t*>(&hp);
    }
}

// ============================================================
// Launch: x, W_v, W_sigma, b_sigma, W_out, b_out
// ============================================================
extern "C" void kernel_launch(void* const* d_in, const int* in_sizes, int n_in,
                              void* d_out, int out_size)
{
    const float* x     = (const float*)d_in[0];
    const float* W_v   = (const float*)d_in[1];
    const float* W_sig = (const float*)d_in[2];
    const float* b_sig = (const float*)d_in[3];
    const float* W_out = (const float*)d_in[4];
    const float* b_out = (const float*)d_in[5];
    float* out = (float*)d_out;

    uint32_t *x16, *wvt16, *wot16;
    float *v, *inv;
    unsigned short *a16;
    cudaGetSymbolAddress((void**)&x16, g_x16);
    cudaGetSymbolAddress((void**)&wvt16, g_wvt16);
    cudaGetSymbolAddress((void**)&wot16, g_wot16);
    cudaGetSymbolAddress((void**)&v, g_v);
    cudaGetSymbolAddress((void**)&inv, g_inv);
    cudaGetSymbolAddress((void**)&a16, g_a16);

    static bool attr_set = false;
    if (!attr_set) {
        cudaFuncSetAttribute(gemm_a16_1p_kernel,
                             cudaFuncAttributeMaxDynamicSharedMemorySize,
                             GEMM2_SMEM_BYTES);
        attr_set = true;
    }

    // x -> fp16 pairs
    {
        const int n4 = M_ROWS * D / 4;
        convert_x16_kernel<<<n4 / 256, 256>>>((const float4*)x, (uint2*)x16, n4);
    }
    // W_v^T, W_out^T -> fp16 pairs
    {
        dim3 grid(INNER / 32, D / 32);
        convert_wt_fp16s_kernel<<<grid, 256>>>(W_v, wvt16, D, INNER);
    }
    {
        dim3 grid(D / 32, INNER / 32);
        convert_wt_fp16s_kernel<<<grid, 256>>>(W_out, wot16, INNER, D);
    }
    // v = x @ W_v  (fp16 1-pass)
    {
        dim3 grid(INNER / 128, M_ROWS / 128);
        gemm_a16_1p_kernel<<<grid, 256, GEMM2_SMEM_BYTES>>>(x16, wvt16, nullptr, v,
                                                            INNER, D);
    }
    // sigma
    sigma_kernel<<<M_ROWS / 8, 256>>>(x, (const float4*)W_sig, b_sig, inv);
    // banded prior @ v -> attn fp16
    {
        dim3 grid(N / RB, HEADS, B);
        band_kernel<<<grid, 256>>>(v, inv, a16);
    }
    // out = attn @ W_out + b_out  (fp16 1-pass)
    {
        dim3 grid(D / 128, M_ROWS / 128);
        gemm_a16_1p_kernel<<<grid, 256, GEMM2_SMEM_BYTES>>>((const uint32_t*)a16,
                                                            wot16, b_out, out,
                                                            D, INNER);
    }
}